// round 10
// baseline (speedup 1.0000x reference)
#include <cuda_runtime.h>
#include <cuda_fp16.h>
#include <cuda_bf16.h>
#include <cstdint>

// Problem constants
#define NTOK   4096      // 64*64 tokens
#define DIM    768
#define NH     12
#define HD     64
#define GRID_HW 64
#define QKSCALE 0.125f   // 64^-0.5
#define LOG2E   1.44269504f
#define M0SHIFT 5.77078016f   // 4.0 * log2(e)
#define NSPLIT 3              // split-KV factor

// ---------------- scratch (device globals; no allocation allowed) ----------
__device__ float  g_q[NH * NTOK * HD];                 // fp32 q, [head][tok][d]
__device__ __align__(16) __half g_k[NH * NTOK * HD];   // fp16 k, [head][tok][d]
__device__ __align__(16) __half g_v[NH * HD * NTOK];   // fp16 v TRANSPOSED [head][d][tok]
__device__ float g_relh[NH * NTOK * HD];               // [head][n][kh]
__device__ float g_relw[NH * NTOK * HD];               // [head][n][kw]
__device__ float g_po[NSPLIT * NH * NTOK * HD];        // split-KV unnormalized O
__device__ float g_pl[NSPLIT * NH * NTOK];             // split-KV partial l
// pre-split GEMM operands
__device__ __align__(16) __nv_bfloat16 g_xh[NTOK * DIM];
__device__ __align__(16) __nv_bfloat16 g_xl[NTOK * DIM];
__device__ __align__(16) __nv_bfloat16 g_wqh[DIM * 3 * DIM];
__device__ __align__(16) __nv_bfloat16 g_wql[DIM * 3 * DIM];
__device__ __align__(16) __half g_wph[DIM * DIM];      // proj weight fp16
__device__ __align__(16) __half g_aoh[NTOK * DIM];     // attention out fp16

// ---------------------------------------------------------------------------
// helpers
// ---------------------------------------------------------------------------
__device__ __forceinline__ float ex2f(float x) {
    float y;
    asm("ex2.approx.f32 %0, %1;" : "=f"(y) : "f"(x));
    return y;
}

__device__ __forceinline__ void mma_bf16(float c[4],
                                         unsigned a0, unsigned a1, unsigned a2, unsigned a3,
                                         unsigned b0, unsigned b1) {
    asm volatile(
        "mma.sync.aligned.m16n8k16.row.col.f32.bf16.bf16.f32 "
        "{%0,%1,%2,%3}, {%4,%5,%6,%7}, {%8,%9}, {%0,%1,%2,%3};\n"
        : "+f"(c[0]), "+f"(c[1]), "+f"(c[2]), "+f"(c[3])
        : "r"(a0), "r"(a1), "r"(a2), "r"(a3), "r"(b0), "r"(b1));
}

__device__ __forceinline__ void mma_f16(float c[4],
                                        unsigned a0, unsigned a1, unsigned a2, unsigned a3,
                                        unsigned b0, unsigned b1) {
    asm volatile(
        "mma.sync.aligned.m16n8k16.row.col.f32.f16.f16.f32 "
        "{%0,%1,%2,%3}, {%4,%5,%6,%7}, {%8,%9}, {%0,%1,%2,%3};\n"
        : "+f"(c[0]), "+f"(c[1]), "+f"(c[2]), "+f"(c[3])
        : "r"(a0), "r"(a1), "r"(a2), "r"(a3), "r"(b0), "r"(b1));
}

__device__ __forceinline__ void ldsm4(unsigned* d, uint32_t addr) {
    asm volatile("ldmatrix.sync.aligned.m8n8.x4.shared.b16 {%0,%1,%2,%3}, [%4];\n"
                 : "=r"(d[0]), "=r"(d[1]), "=r"(d[2]), "=r"(d[3]) : "r"(addr));
}

__device__ __forceinline__ void ldsm4t(unsigned* d, uint32_t addr) {
    asm volatile("ldmatrix.sync.aligned.m8n8.x4.trans.shared.b16 {%0,%1,%2,%3}, [%4];\n"
                 : "=r"(d[0]), "=r"(d[1]), "=r"(d[2]), "=r"(d[3]) : "r"(addr));
}

__device__ __forceinline__ void cp16(uint32_t dst, const void* src) {
    asm volatile("cp.async.cg.shared.global [%0], [%1], 16;\n" :: "r"(dst), "l"(src));
}
#define CP_COMMIT() asm volatile("cp.async.commit_group;\n")

__device__ __forceinline__ unsigned packh2(float x, float y) {
    __half2 h = __floats2half2_rn(x, y);
    return *reinterpret_cast<unsigned*>(&h);
}

// ---------------------------------------------------------------------------
// conversion kernels (run once per launch; a few microseconds total)
// ---------------------------------------------------------------------------
__global__ void conv_split_kernel(const float* __restrict__ in,
                                  __nv_bfloat16* __restrict__ hi,
                                  __nv_bfloat16* __restrict__ lo, int n4)
{
    const int i = blockIdx.x * 256 + threadIdx.x;
    if (i >= n4) return;
    float4 v = ((const float4*)in)[i];
    __nv_bfloat162 h0 = __float22bfloat162_rn(make_float2(v.x, v.y));
    __nv_bfloat162 h1 = __float22bfloat162_rn(make_float2(v.z, v.w));
    float lx = v.x - __bfloat162float(__low2bfloat16(h0));
    float ly = v.y - __bfloat162float(__high2bfloat16(h0));
    float lz = v.z - __bfloat162float(__low2bfloat16(h1));
    float lw = v.w - __bfloat162float(__high2bfloat16(h1));
    __nv_bfloat162 l0 = __float22bfloat162_rn(make_float2(lx, ly));
    __nv_bfloat162 l1 = __float22bfloat162_rn(make_float2(lz, lw));
    ((uint2*)hi)[i] = make_uint2(*(unsigned*)&h0, *(unsigned*)&h1);
    ((uint2*)lo)[i] = make_uint2(*(unsigned*)&l0, *(unsigned*)&l1);
}

__global__ void conv_half_kernel(const float* __restrict__ in,
                                 __half* __restrict__ out, int n4)
{
    const int i = blockIdx.x * 256 + threadIdx.x;
    if (i >= n4) return;
    float4 v = ((const float4*)in)[i];
    __half2 h0 = __floats2half2_rn(v.x, v.y);
    __half2 h1 = __floats2half2_rn(v.z, v.w);
    ((uint2*)out)[i] = make_uint2(*(unsigned*)&h0, *(unsigned*)&h1);
}

// ---------------------------------------------------------------------------
// bf16 x3 GEMM for QKV, operands PRE-SPLIT in gmem (unchanged from round 9)
// ---------------------------------------------------------------------------
#define AST 20
#define BST 68
#define A_STAGE (128 * AST)
#define B_STAGE (16 * BST)

__global__ void __launch_bounds__(256)
gemm_qkv_kernel(const __nv_bfloat16* __restrict__ Ah_g,
                const __nv_bfloat16* __restrict__ Al_g,
                const __nv_bfloat16* __restrict__ Bh_g,
                const __nv_bfloat16* __restrict__ Bl_g,
                const float* __restrict__ bias)
{
    const int N = 3 * DIM, K = DIM;
    extern __shared__ float gsm[];
    float* As  = gsm;
    float* Bhs = As  + 2 * A_STAGE;
    float* Bls = Bhs + 2 * B_STAGE;

    const int bx = blockIdx.x, by = blockIdx.y;
    const int t  = threadIdx.x;
    const int lane = t & 31, w = t >> 5;
    const int r = lane >> 2, c = lane & 3;
    const int wm = w >> 1, wn = w & 1;
    const int m0 = by * 128, n0 = bx * 128;
    const int mw = wm * 32,  nw = wn * 64;

    const int aRow  = (lane & 7) + ((lane >> 3) & 1) * 8;
    const int aColB = (lane >> 4) * 16;
    const int bRow  = (lane & 7) + ((lane >> 3) & 1) * 8;
    const int bColB = ((lane >> 4) & 1) * 16;

    const int am  = t >> 1;
    const int akh = (t & 1);
    const int bk  = t >> 4;
    const int bn4 = t & 15;

    const __nv_bfloat16* Agh = Ah_g + (m0 + am) * K + akh * 8;
    const __nv_bfloat16* Agl = Al_g + (m0 + am) * K + akh * 8;
    const __nv_bfloat16* Bgh = Bh_g + n0 + bn4 * 4;
    const __nv_bfloat16* Bgl = Bl_g + n0 + bn4 * 4;

    const uint32_t as_b  = (uint32_t)__cvta_generic_to_shared(As);
    const uint32_t bhs_b = (uint32_t)__cvta_generic_to_shared(Bhs);
    const uint32_t bls_b = (uint32_t)__cvta_generic_to_shared(Bls);

    uint4 a4h, a4l;
    uint2 b4h[2], b4l[2];
    float acc[2][8][4];
#pragma unroll
    for (int mg = 0; mg < 2; mg++)
#pragma unroll
        for (int ng = 0; ng < 8; ng++)
#pragma unroll
            for (int j = 0; j < 4; j++) acc[mg][ng][j] = 0.f;

    const int nk = K / 16;

    #define QKV_LDG(i) do {                                              \
        const int kg_ = (i) * 16;                                        \
        a4h = *(const uint4*)(Agh + kg_);                                \
        a4l = *(const uint4*)(Agl + kg_);                                \
        const __nv_bfloat16* bph_ = Bgh + (int64_t)(kg_ + bk) * N;       \
        const __nv_bfloat16* bpl_ = Bgl + (int64_t)(kg_ + bk) * N;       \
        b4h[0] = *(const uint2*)(bph_);                                  \
        b4h[1] = *(const uint2*)(bph_ + 64);                             \
        b4l[0] = *(const uint2*)(bpl_);                                  \
        b4l[1] = *(const uint2*)(bpl_ + 64);                             \
    } while (0)

    #define QKV_STS(s) do {                                              \
        float* as = As + (s) * A_STAGE;                                  \
        float* bh = Bhs + (s) * B_STAGE;                                 \
        float* bl = Bls + (s) * B_STAGE;                                 \
        *(uint4*)&as[am * AST + akh * 4]     = a4h;                      \
        *(uint4*)&as[am * AST + akh * 4 + 8] = a4l;                      \
        const int wo = bk * BST + bn4 * 2;                               \
        *(uint2*)&bh[wo]      = b4h[0];                                  \
        *(uint2*)&bh[wo + 32] = b4h[1];                                  \
        *(uint2*)&bl[wo]      = b4l[0];                                  \
        *(uint2*)&bl[wo + 32] = b4l[1];                                  \
    } while (0)

    QKV_LDG(0);
    QKV_STS(0);
    QKV_LDG(1);
    __syncthreads();

    for (int i = 0; i < nk; i++) {
        const int s = i & 1;
        const uint32_t aB  = as_b  + (uint32_t)(s * A_STAGE * 4) + (mw + aRow) * 80 + aColB;
        const uint32_t bhB = bhs_b + (uint32_t)(s * B_STAGE * 4) + bRow * 272 + bColB;
        const uint32_t blB = bls_b + (uint32_t)(s * B_STAGE * 4) + bRow * 272 + bColB;

        unsigned ah[2][4], al_[2][4];
#pragma unroll
        for (int mg = 0; mg < 2; mg++) {
            ldsm4(ah[mg],  aB + (uint32_t)(mg * 16 * 80));
            ldsm4(al_[mg], aB + (uint32_t)(mg * 16 * 80 + 32));
        }
#pragma unroll
        for (int g = 0; g < 4; g++) {
            const uint32_t noff = (uint32_t)((nw + g * 16) * 2);
            unsigned bh[4], bl[4];
            ldsm4t(bh, bhB + noff);
            ldsm4t(bl, blB + noff);
#pragma unroll
            for (int half = 0; half < 2; half++) {
                const unsigned b0h = bh[half * 2], b1h = bh[half * 2 + 1];
                const unsigned b0l = bl[half * 2], b1l = bl[half * 2 + 1];
                const int ng = g * 2 + half;
#pragma unroll
                for (int mg = 0; mg < 2; mg++) {
                    mma_bf16(acc[mg][ng], al_[mg][0], al_[mg][1], al_[mg][2], al_[mg][3], b0h, b1h);
                    mma_bf16(acc[mg][ng], ah[mg][0],  ah[mg][1],  ah[mg][2],  ah[mg][3],  b0l, b1l);
                    mma_bf16(acc[mg][ng], ah[mg][0],  ah[mg][1],  ah[mg][2],  ah[mg][3],  b0h, b1h);
                }
            }
        }

        if (i + 1 < nk) {
            QKV_STS((i + 1) & 1);
            if (i + 2 < nk) QKV_LDG(i + 2);
        }
        __syncthreads();
    }

    // epilogue: scatter q/k/v
#pragma unroll
    for (int mg = 0; mg < 2; mg++) {
        const int row0 = m0 + mw + mg * 16 + r;
        const int row1 = row0 + 8;
#pragma unroll
        for (int ng = 0; ng < 8; ng++) {
            const int col = n0 + nw + ng * 8 + 2 * c;
            const float bs0 = bias[col], bs1 = bias[col + 1];
            float v00 = acc[mg][ng][0] + bs0, v01 = acc[mg][ng][1] + bs1;
            float v10 = acc[mg][ng][2] + bs0, v11 = acc[mg][ng][3] + bs1;
            const int part = col / DIM;
            const int rest = col - part * DIM;
            const int head = rest >> 6;
            const int d0   = rest & 63;
            if (part == 0) {
                *(float2*)&g_q[(head * NTOK + row0) * HD + d0] = make_float2(v00, v01);
                *(float2*)&g_q[(head * NTOK + row1) * HD + d0] = make_float2(v10, v11);
            } else if (part == 1) {
                *(__half2*)&g_k[(head * NTOK + row0) * HD + d0] = __floats2half2_rn(v00, v01);
                *(__half2*)&g_k[(head * NTOK + row1) * HD + d0] = __floats2half2_rn(v10, v11);
            } else {
                __half* vt = g_v + head * HD * NTOK;
                vt[(d0    ) * NTOK + row0] = __float2half_rn(v00);
                vt[(d0 + 1) * NTOK + row0] = __float2half_rn(v01);
                vt[(d0    ) * NTOK + row1] = __float2half_rn(v10);
                vt[(d0 + 1) * NTOK + row1] = __float2half_rn(v11);
            }
        }
    }
}

// ---------------------------------------------------------------------------
// plain fp16 GEMM for the output projection (unchanged from round 9)
// ---------------------------------------------------------------------------
#define ASTP 12
#define A_STAGE_P (128 * ASTP)
#define B_STAGE_P (16 * BST)

__global__ void __launch_bounds__(256)
gemm_proj_kernel(const __half* __restrict__ Ah_g,
                 const __half* __restrict__ Bh_g,
                 const float* __restrict__ bias,
                 float* __restrict__ C)
{
    const int N = DIM, K = DIM;
    extern __shared__ float gsm[];
    float* As  = gsm;
    float* Bhs = As + 2 * A_STAGE_P;

    const int bx = blockIdx.x, by = blockIdx.y;
    const int t  = threadIdx.x;
    const int lane = t & 31, w = t >> 5;
    const int r = lane >> 2, c = lane & 3;
    const int wm = w >> 1, wn = w & 1;
    const int m0 = by * 128, n0 = bx * 128;
    const int mw = wm * 32,  nw = wn * 64;

    const int aRow  = (lane & 7) + ((lane >> 3) & 1) * 8;
    const int aColB = (lane >> 4) * 16;
    const int bRow  = (lane & 7) + ((lane >> 3) & 1) * 8;
    const int bColB = ((lane >> 4) & 1) * 16;

    const int am  = t >> 1;
    const int akh = (t & 1);
    const int bk  = t >> 4;
    const int bn4 = t & 15;

    const __half* Ag = Ah_g + (m0 + am) * K + akh * 8;
    const __half* Bg = Bh_g + n0 + bn4 * 4;

    const uint32_t as_b  = (uint32_t)__cvta_generic_to_shared(As);
    const uint32_t bhs_b = (uint32_t)__cvta_generic_to_shared(Bhs);

    uint4 a4;
    uint2 b4[2];
    float acc[2][8][4];
#pragma unroll
    for (int mg = 0; mg < 2; mg++)
#pragma unroll
        for (int ng = 0; ng < 8; ng++)
#pragma unroll
            for (int j = 0; j < 4; j++) acc[mg][ng][j] = 0.f;

    const int nk = K / 16;

    #define PROJ_LDG(i) do {                                             \
        const int kg_ = (i) * 16;                                        \
        a4 = *(const uint4*)(Ag + kg_);                                  \
        const __half* bp_ = Bg + (int64_t)(kg_ + bk) * N;                \
        b4[0] = *(const uint2*)(bp_);                                    \
        b4[1] = *(const uint2*)(bp_ + 64);                               \
    } while (0)

    #define PROJ_STS(s) do {                                             \
        float* as = As + (s) * A_STAGE_P;                                \
        float* bh = Bhs + (s) * B_STAGE_P;                               \
        *(uint4*)&as[am * ASTP + akh * 4] = a4;                          \
        const int wo = bk * BST + bn4 * 2;                               \
        *(uint2*)&bh[wo]      = b4[0];                                   \
        *(uint2*)&bh[wo + 32] = b4[1];                                   \
    } while (0)

    PROJ_LDG(0);
    PROJ_STS(0);
    PROJ_LDG(1);
    __syncthreads();

    for (int i = 0; i < nk; i++) {
        const int s = i & 1;
        const uint32_t aB  = as_b  + (uint32_t)(s * A_STAGE_P * 4) + (mw + aRow) * 48 + aColB;
        const uint32_t bhB = bhs_b + (uint32_t)(s * B_STAGE_P * 4) + bRow * 272 + bColB;

        unsigned ah[2][4];
#pragma unroll
        for (int mg = 0; mg < 2; mg++)
            ldsm4(ah[mg], aB + (uint32_t)(mg * 16 * 48));
#pragma unroll
        for (int g = 0; g < 4; g++) {
            unsigned bh[4];
            ldsm4t(bh, bhB + (uint32_t)((nw + g * 16) * 2));
#pragma unroll
            for (int half = 0; half < 2; half++) {
                const unsigned b0 = bh[half * 2], b1 = bh[half * 2 + 1];
                const int ng = g * 2 + half;
#pragma unroll
                for (int mg = 0; mg < 2; mg++)
                    mma_f16(acc[mg][ng], ah[mg][0], ah[mg][1], ah[mg][2], ah[mg][3], b0, b1);
            }
        }

        if (i + 1 < nk) {
            PROJ_STS((i + 1) & 1);
            if (i + 2 < nk) PROJ_LDG(i + 2);
        }
        __syncthreads();
    }

#pragma unroll
    for (int mg = 0; mg < 2; mg++) {
        const int row0 = m0 + mw + mg * 16 + r;
        const int row1 = row0 + 8;
#pragma unroll
        for (int ng = 0; ng < 8; ng++) {
            const int col = n0 + nw + ng * 8 + 2 * c;
            const float bs0 = bias[col], bs1 = bias[col + 1];
            *(float2*)&C[(int64_t)row0 * N + col] =
                make_float2(acc[mg][ng][0] + bs0, acc[mg][ng][1] + bs1);
            *(float2*)&C[(int64_t)row1 * N + col] =
                make_float2(acc[mg][ng][2] + bs0, acc[mg][ng][3] + bs1);
        }
    }
}

// ---------------------------------------------------------------------------
// rel-pos dot products (fp32, both modes via blockIdx.z)
// ---------------------------------------------------------------------------
__global__ void relpos_kernel(const float* __restrict__ gq,
                              const float* __restrict__ relh,
                              const float* __restrict__ relw,
                              float* __restrict__ outh,
                              float* __restrict__ outw)
{
    __shared__ float qs[64][65];
    __shared__ float rp[64][65];

    const int fixed = blockIdx.x;
    const int head  = blockIdx.y;
    const int mode  = blockIdx.z;
    const int t     = threadIdx.x;
    const float* relpos = mode ? relw : relh;
    float* out = mode ? outw : outh;

    if (mode == 0) {
        const float* base = gq + (head * NTOK + fixed * 64) * HD;
        for (int e = t; e < 4096; e += 256) qs[e >> 6][e & 63] = base[e];
    } else {
        const float* base = gq + (head * NTOK + fixed) * HD;
        for (int e = t; e < 4096; e += 256) {
            int row = e >> 6, c = e & 63;
            qs[row][c] = base[row * (64 * HD) + c];
        }
    }
    for (int e = t; e < 4096; e += 256) {
        int k = e >> 6, c = e & 63;
        rp[k][c] = relpos[(fixed - k + 63) * HD + c];
    }
    __syncthreads();

    const int qi = t >> 2;
    const int k0 = (t & 3) << 4;

    float accv[16];
#pragma unroll
    for (int j = 0; j < 16; j++) accv[j] = 0.f;

    for (int d = 0; d < 64; d++) {
        float qv = qs[qi][d];
#pragma unroll
        for (int j = 0; j < 16; j++) accv[j] += qv * rp[k0 + j][d];
    }

    const int n = (mode == 0) ? (fixed * 64 + qi) : (qi * 64 + fixed);
    float* op = out + (head * NTOK + n) * HD + k0;
#pragma unroll
    for (int j = 0; j < 16; j++) op[j] = accv[j];
}

// ---------------------------------------------------------------------------
// Flash attention v10: register-resident P (C-frag of S == A-frag of PV),
// fixed-shift softmax, fp16 MMA, 3-stage cp.async, split-KV x3.
// 128 threads = 4 warps x 32 Q rows. No smem traffic for P, no syncwarps.
// ---------------------------------------------------------------------------
#define STRH      72
#define ROW_B     144
#define KV_TILE_B (64 * ROW_B)               // 9216 B per tile
#define PQ_B      (128 * ROW_B)              // 18432 B (Q staging)
#define FLASH_SMEM_B (6 * KV_TILE_B + PQ_B)  // 73728 B

__global__ void __launch_bounds__(128, 2)
flash_v10_kernel(const float* __restrict__ gq,
                 const __half* __restrict__ gk,
                 const __half* __restrict__ gvt,
                 const float* __restrict__ grh,
                 const float* __restrict__ grw,
                 float* __restrict__ po,
                 float* __restrict__ pl)
{
    extern __shared__ char smc[];
    char*   Ksc = smc;                        // 3 stages x 64 x 144B
    char*   Vsc = smc + 3 * KV_TILE_B;        // 3 stages x 64 x 144B
    __half* PQh = (__half*)(smc + 6 * KV_TILE_B);   // Q staging only

    const int qt   = blockIdx.x;
    const int head = blockIdx.y;
    const int z    = blockIdx.z;      // KV third
    const int ktb  = (z == 0) ? 0 : (22 + 21 * (z - 1));   // 0, 22, 43
    const int nit  = (z == 0) ? 22 : 21;
    const int t    = threadIdx.x;
    const int lane = t & 31;
    const int w    = t >> 5;
    const int r    = lane >> 2;
    const int c    = lane & 3;
    const int mbase = w * 32;

    const float*  qb   = gq  + (head * NTOK + qt * 128) * HD;
    const __half* kb0  = gk  + head * NTOK * HD;
    const char*   vtb0 = (const char*)(gvt + head * HD * NTOK);
    const float*  rhb  = grh + (head * NTOK + qt * 128 + mbase) * HD;
    const float*  rwb  = grw + (head * NTOK + qt * 128 + mbase) * HD;

    const uint32_t ks_sm = (uint32_t)__cvta_generic_to_shared(Ksc);
    const uint32_t vs_sm = (uint32_t)__cvta_generic_to_shared(Vsc);
    const uint32_t pq_sm = (uint32_t)__cvta_generic_to_shared(PQh);

    #define LOAD_KV(st, kt) do {                                              \
        const char* kb_ = (const char*)(kb0 + (kt) * 64 * HD);                \
        const uint32_t kd_ = ks_sm + (uint32_t)((st) * KV_TILE_B);            \
        const uint32_t vd_ = vs_sm + (uint32_t)((st) * KV_TILE_B);            \
        _Pragma("unroll")                                                     \
        for (int i_ = 0; i_ < 4; i_++) {                                      \
            const int ch_ = t + i_ * 128;                                     \
            const int row_ = ch_ >> 3, co_ = (ch_ & 7) * 16;                  \
            cp16(kd_ + row_ * ROW_B + co_, kb_ + row_ * 128 + co_);           \
            cp16(vd_ + row_ * ROW_B + co_,                                    \
                 vtb0 + row_ * (NTOK * 2) + (kt) * 128 + co_);                \
        }                                                                     \
    } while (0)

    // prologue: prefetch tiles ktb, ktb+1
    LOAD_KV(0, ktb);     CP_COMMIT();
    LOAD_KV(1, ktb + 1); CP_COMMIT();

    // stage Q (scaled into log2 domain, fp16)
    const float qsc = QKSCALE * LOG2E;
    for (int e = t; e < 128 * 32; e += 128) {
        const int row = e >> 5, c2 = (e & 31) * 2;
        float2 v = *(const float2*)(qb + row * HD + c2);
        *(__half2*)(PQh + row * STRH + c2) = __floats2half2_rn(v.x * qsc, v.y * qsc);
    }
    __syncthreads();

    // Q fragments (persist)
    const uint32_t aBase = pq_sm + (uint32_t)((mbase + (lane & 15)) * ROW_B
                                              + (lane >> 4) * 16);
    unsigned qa[2][4][4];
#pragma unroll
    for (int mb = 0; mb < 2; mb++)
#pragma unroll
        for (int kk = 0; kk < 4; kk++)
            ldsm4(qa[mb][kk], aBase + (uint32_t)(mb * 16 * ROW_B + kk * 32));
    __syncwarp();

    // rw bias in log2 domain, packed fp16x2: [mb][rowgroup][n]
    __half2 rwh[2][2][8];
#pragma unroll
    for (int mb = 0; mb < 2; mb++)
#pragma unroll
        for (int rg = 0; rg < 2; rg++)
#pragma unroll
            for (int n = 0; n < 8; n++) {
                float2 v = *(const float2*)&rwb[(mb * 16 + rg * 8 + r) * HD + n * 8 + 2 * c];
                rwh[mb][rg][n] = __floats2half2_rn(v.x * LOG2E, v.y * LOG2E);
            }

    float O[2][8][4];
#pragma unroll
    for (int mb = 0; mb < 2; mb++)
#pragma unroll
        for (int n = 0; n < 8; n++)
#pragma unroll
            for (int j = 0; j < 4; j++) O[mb][n][j] = 0.f;
    float l_[2][2] = {{0.f, 0.f}, {0.f, 0.f}};

    for (int it = 0; it < nit; it++) {
        const int kt = ktb + it;
        const int s  = it % 3;

        asm volatile("cp.async.wait_group 1;\n");
        __syncthreads();   // tile kt ready; all warps done with stage (it+2)%3

        if (it + 2 < nit) LOAD_KV((it + 2) % 3, kt + 2);
        CP_COMMIT();

        // rh bias (log2 domain, -M0 shift folded in)
        float rh[2][2];
#pragma unroll
        for (int mb = 0; mb < 2; mb++) {
            rh[mb][0] = fmaf(__ldg(&rhb[(mb * 16 + r) * HD + kt]),     LOG2E, -M0SHIFT);
            rh[mb][1] = fmaf(__ldg(&rhb[(mb * 16 + 8 + r) * HD + kt]), LOG2E, -M0SHIFT);
        }

        const uint32_t kS = ks_sm + (uint32_t)(s * KV_TILE_B)
                              + (lane & 15) * ROW_B + (lane >> 4) * 16;
        const uint32_t vS = vs_sm + (uint32_t)(s * KV_TILE_B)
                              + (lane & 15) * ROW_B + (lane >> 4) * 16;

        // ---- S = Q K^T over full 64 keys ----
        float S[2][8][4];
#pragma unroll
        for (int mb = 0; mb < 2; mb++)
#pragma unroll
            for (int n = 0; n < 8; n++)
#pragma unroll
                for (int j = 0; j < 4; j++) S[mb][n][j] = 0.f;

#pragma unroll
        for (int kk = 0; kk < 4; kk++) {
#pragma unroll
            for (int g = 0; g < 4; g++) {     // 4 n16 key groups
                unsigned bb[4];
                ldsm4(bb, kS + (uint32_t)(g * 16 * ROW_B + kk * 32));
                mma_f16(S[0][g*2],   qa[0][kk][0], qa[0][kk][1], qa[0][kk][2], qa[0][kk][3], bb[0], bb[2]);
                mma_f16(S[0][g*2+1], qa[0][kk][0], qa[0][kk][1], qa[0][kk][2], qa[0][kk][3], bb[1], bb[3]);
                mma_f16(S[1][g*2],   qa[1][kk][0], qa[1][kk][1], qa[1][kk][2], qa[1][kk][3], bb[0], bb[2]);
                mma_f16(S[1][g*2+1], qa[1][kk][0], qa[1][kk][1], qa[1][kk][2], qa[1][kk][3], bb[1], bb[3]);
            }
        }

        // ---- fixed-shift softmax, P packed straight into A-fragments ----
        // C-frag (c0,c1 row r / c2,c3 row r+8 of n8 tile) -> packed half2:
        //   pp0[mb][n] = h2(p0,p1)  (row r),  pp1[mb][n] = h2(p2,p3)  (row r+8)
        unsigned pp0[2][8], pp1[2][8];
#pragma unroll
        for (int mb = 0; mb < 2; mb++) {
            const float a0 = rh[mb][0];
            const float a1 = rh[mb][1];
            float s0 = 0.f, s1 = 0.f;
#pragma unroll
            for (int n = 0; n < 8; n++) {
                float2 w0 = __half22float2(rwh[mb][0][n]);
                float2 w1 = __half22float2(rwh[mb][1][n]);
                float p0 = ex2f(S[mb][n][0] + a0 + w0.x);
                float p1 = ex2f(S[mb][n][1] + a0 + w0.y);
                float p2 = ex2f(S[mb][n][2] + a1 + w1.x);
                float p3 = ex2f(S[mb][n][3] + a1 + w1.y);
                s0 += p0 + p1;  s1 += p2 + p3;
                pp0[mb][n] = packh2(p0, p1);
                pp1[mb][n] = packh2(p2, p3);
            }
            l_[mb][0] += s0;  l_[mb][1] += s1;
        }

        // ---- O += P V (64 keys = 4 k16 steps), P from registers ----
#pragma unroll
        for (int kk2 = 0; kk2 < 4; kk2++) {
            const unsigned a00 = pp0[0][2*kk2], a01 = pp1[0][2*kk2];
            const unsigned a02 = pp0[0][2*kk2+1], a03 = pp1[0][2*kk2+1];
            const unsigned a10 = pp0[1][2*kk2], a11 = pp1[1][2*kk2];
            const unsigned a12 = pp0[1][2*kk2+1], a13 = pp1[1][2*kk2+1];
#pragma unroll
            for (int p = 0; p < 4; p++) {      // d16 groups
                unsigned vv[4];
                ldsm4(vv, vS + (uint32_t)(p * 16 * ROW_B + kk2 * 32));
                mma_f16(O[0][p*2],   a00, a01, a02, a03, vv[0], vv[2]);
                mma_f16(O[0][p*2+1], a00, a01, a02, a03, vv[1], vv[3]);
                mma_f16(O[1][p*2],   a10, a11, a12, a13, vv[0], vv[2]);
                mma_f16(O[1][p*2+1], a10, a11, a12, a13, vv[1], vv[3]);
            }
        }
    }

    // ---- epilogue: reduce l across the 4 lanes of each row, store partials ----
#pragma unroll
    for (int mb = 0; mb < 2; mb++)
#pragma unroll
        for (int rg = 0; rg < 2; rg++) {
            float l = l_[mb][rg];
            l += __shfl_xor_sync(0xffffffffu, l, 1);
            l += __shfl_xor_sync(0xffffffffu, l, 2);
            l_[mb][rg] = l;
        }

    const int pz = z * NH * NTOK + head * NTOK;
#pragma unroll
    for (int mb = 0; mb < 2; mb++) {
        const int row0 = qt * 128 + mbase + mb * 16 + r;
        const int row1 = row0 + 8;
        if (c == 0) {
            pl[pz + row0] = l_[mb][0];
            pl[pz + row1] = l_[mb][1];
        }
#pragma unroll
        for (int n = 0; n < 8; n++) {
            const int col = n * 8 + 2 * c;
            *(float2*)&po[(pz + row0) * HD + col] = make_float2(O[mb][n][0], O[mb][n][1]);
            *(float2*)&po[(pz + row1) * HD + col] = make_float2(O[mb][n][2], O[mb][n][3]);
        }
    }
}

// ---------------------------------------------------------------------------
// merge the three KV-third partials -> g_aoh (fp16, feeds proj GEMM)
// ---------------------------------------------------------------------------
__global__ void merge_kernel(const float* __restrict__ po,
                             const float* __restrict__ pl,
                             __half* __restrict__ aoh)
{
    const int gid = blockIdx.x * 256 + threadIdx.x;
    const int dp  = (gid & 7) * 8;
    const int hr  = gid >> 3;
    const int head = hr >> 12, row = hr & 4095;
    const int S = NH * NTOK;

    const float inv = 1.0f / (pl[hr] + pl[S + hr] + pl[2 * S + hr]);

    const float* o0 = po + (size_t)hr * HD + dp;
    const float* o1 = po + (size_t)(S + hr) * HD + dp;
    const float* o2 = po + (size_t)(2 * S + hr) * HD + dp;
    __half* dst = aoh + row * DIM + head * HD + dp;

    uint4 outw;
    unsigned* ow = (unsigned*)&outw;
#pragma unroll
    for (int j = 0; j < 8; j += 2) {
        float x = (o0[j]     + o1[j]     + o2[j])     * inv;
        float y = (o0[j + 1] + o1[j + 1] + o2[j + 1]) * inv;
        __half2 h = __floats2half2_rn(x, y);
        ow[j >> 1] = *(unsigned*)&h;
    }
    *(uint4*)dst = outw;
}

// ---------------------------------------------------------------------------
extern "C" void kernel_launch(void* const* d_in, const int* in_sizes, int n_in,
                              void* d_out, int out_size)
{
    const float* x        = (const float*)d_in[0];
    const float* w_qkv    = (const float*)d_in[1];
    const float* b_qkv    = (const float*)d_in[2];
    const float* w_proj   = (const float*)d_in[3];
    const float* b_proj   = (const float*)d_in[4];
    const float* rel_h    = (const float*)d_in[5];
    const float* rel_w    = (const float*)d_in[6];
    float* out = (float*)d_out;

    float *gq, *grh, *grw, *gpo, *gpl;
    __half *gk, *gv, *gwph, *gaoh;
    __nv_bfloat16 *gxh, *gxl, *gwqh, *gwql;
    cudaGetSymbolAddress((void**)&gq,   g_q);
    cudaGetSymbolAddress((void**)&gk,   g_k);
    cudaGetSymbolAddress((void**)&gv,   g_v);
    cudaGetSymbolAddress((void**)&grh,  g_relh);
    cudaGetSymbolAddress((void**)&grw,  g_relw);
    cudaGetSymbolAddress((void**)&gpo,  g_po);
    cudaGetSymbolAddress((void**)&gpl,  g_pl);
    cudaGetSymbolAddress((void**)&gxh,  g_xh);
    cudaGetSymbolAddress((void**)&gxl,  g_xl);
    cudaGetSymbolAddress((void**)&gwqh, g_wqh);
    cudaGetSymbolAddress((void**)&gwql, g_wql);
    cudaGetSymbolAddress((void**)&gwph, g_wph);
    cudaGetSymbolAddress((void**)&gaoh, g_aoh);

    // 0) pre-split / convert operands
    conv_split_kernel<<<(NTOK * DIM / 4 + 255) / 256, 256>>>(x, gxh, gxl, NTOK * DIM / 4);
    conv_split_kernel<<<(DIM * 3 * DIM / 4 + 255) / 256, 256>>>(w_qkv, gwqh, gwql, DIM * 3 * DIM / 4);
    conv_half_kernel<<<(DIM * DIM / 4 + 255) / 256, 256>>>(w_proj, gwph, DIM * DIM / 4);

    // 1) QKV GEMM (bf16x3, pre-split operands)
    static const int GEMM_SMEM = (2 * A_STAGE + 4 * B_STAGE) * (int)sizeof(float);  // 37,888 B
    cudaFuncSetAttribute(gemm_qkv_kernel,
                         cudaFuncAttributeMaxDynamicSharedMemorySize, GEMM_SMEM);
    gemm_qkv_kernel<<<dim3(3 * DIM / 128, NTOK / 128), 256, GEMM_SMEM>>>(
        gxh, gxl, gwqh, gwql, b_qkv);

    // 2) rel_h / rel_w (fused)
    relpos_kernel<<<dim3(GRID_HW, NH, 2), 256>>>(gq, rel_h, rel_w, grh, grw);

    // 3) flash attention v10 (register P, split-KV x3)
    cudaFuncSetAttribute(flash_v10_kernel,
                         cudaFuncAttributeMaxDynamicSharedMemorySize, FLASH_SMEM_B);
    flash_v10_kernel<<<dim3(NTOK / 128, NH, NSPLIT), 128, FLASH_SMEM_B>>>(
        gq, gk, gv, grh, grw, gpo, gpl);

    // 4) merge partials -> fp16 ao
    merge_kernel<<<NH * NTOK * 8 / 256, 256>>>(gpo, gpl, gaoh);

    // 5) output projection (fp16 x1)
    static const int PROJ_SMEM = (2 * A_STAGE_P + 2 * B_STAGE_P) * (int)sizeof(float);  // 20,992 B
    cudaFuncSetAttribute(gemm_proj_kernel,
                         cudaFuncAttributeMaxDynamicSharedMemorySize, PROJ_SMEM);
    gemm_proj_kernel<<<dim3(DIM / 128, NTOK / 128), 256, PROJ_SMEM>>>(
        gaoh, gwph, b_proj, out);
}

// round 11
// speedup vs baseline: 1.1341x; 1.1341x over previous
#include <cuda_runtime.h>
#include <cuda_fp16.h>
#include <cuda_bf16.h>
#include <cstdint>

// Problem constants
#define NTOK   4096      // 64*64 tokens
#define DIM    768
#define NH     12
#define HD     64
#define GRID_HW 64
#define QKSCALE 0.125f   // 64^-0.5
#define LOG2E   1.44269504f
#define M0SHIFT 5.77078016f   // 4.0 * log2(e)
#define NSPLIT 3              // split-KV factor

// ---------------- scratch (device globals; no allocation allowed) ----------
__device__ float  g_q[NH * NTOK * HD];                 // fp32 q, [head][tok][d]
__device__ __align__(16) __half g_k[NH * NTOK * HD];   // fp16 k, [head][tok][d]
__device__ __align__(16) __half g_v[NH * HD * NTOK];   // fp16 v TRANSPOSED [head][d][tok]
__device__ float g_relh[NH * NTOK * HD];               // [head][n][kh]
__device__ float g_relw[NH * NTOK * HD];               // [head][n][kw]
__device__ float g_po[NSPLIT * NH * NTOK * HD];        // split-KV unnormalized O
__device__ float g_pl[NSPLIT * NH * NTOK];             // split-KV partial l
// fp16 GEMM operands
__device__ __align__(16) __half g_xh[NTOK * DIM];      // x fp16
__device__ __align__(16) __half g_wqh[DIM * 3 * DIM];  // w_qkv fp16
__device__ __align__(16) __half g_wph[DIM * DIM];      // w_proj fp16
__device__ __align__(16) __half g_aoh[NTOK * DIM];     // attention out fp16

// ---------------------------------------------------------------------------
// helpers
// ---------------------------------------------------------------------------
__device__ __forceinline__ float ex2f(float x) {
    float y;
    asm("ex2.approx.f32 %0, %1;" : "=f"(y) : "f"(x));
    return y;
}

__device__ __forceinline__ void mma_f16(float c[4],
                                        unsigned a0, unsigned a1, unsigned a2, unsigned a3,
                                        unsigned b0, unsigned b1) {
    asm volatile(
        "mma.sync.aligned.m16n8k16.row.col.f32.f16.f16.f32 "
        "{%0,%1,%2,%3}, {%4,%5,%6,%7}, {%8,%9}, {%0,%1,%2,%3};\n"
        : "+f"(c[0]), "+f"(c[1]), "+f"(c[2]), "+f"(c[3])
        : "r"(a0), "r"(a1), "r"(a2), "r"(a3), "r"(b0), "r"(b1));
}

__device__ __forceinline__ void ldsm4(unsigned* d, uint32_t addr) {
    asm volatile("ldmatrix.sync.aligned.m8n8.x4.shared.b16 {%0,%1,%2,%3}, [%4];\n"
                 : "=r"(d[0]), "=r"(d[1]), "=r"(d[2]), "=r"(d[3]) : "r"(addr));
}

__device__ __forceinline__ void ldsm4t(unsigned* d, uint32_t addr) {
    asm volatile("ldmatrix.sync.aligned.m8n8.x4.trans.shared.b16 {%0,%1,%2,%3}, [%4];\n"
                 : "=r"(d[0]), "=r"(d[1]), "=r"(d[2]), "=r"(d[3]) : "r"(addr));
}

__device__ __forceinline__ void cp16(uint32_t dst, const void* src) {
    asm volatile("cp.async.cg.shared.global [%0], [%1], 16;\n" :: "r"(dst), "l"(src));
}
#define CP_COMMIT() asm volatile("cp.async.commit_group;\n")

// ---------------------------------------------------------------------------
// conversion kernel (fp32 -> fp16), vectorized
// ---------------------------------------------------------------------------
__global__ void conv_half_kernel(const float* __restrict__ in,
                                 __half* __restrict__ out, int n4)
{
    const int i = blockIdx.x * 256 + threadIdx.x;
    if (i >= n4) return;
    float4 v = ((const float4*)in)[i];
    __half2 h0 = __floats2half2_rn(v.x, v.y);
    __half2 h1 = __floats2half2_rn(v.z, v.w);
    ((uint2*)out)[i] = make_uint2(*(unsigned*)&h0, *(unsigned*)&h1);
}

// ---------------------------------------------------------------------------
// fp16 x1 GEMM, 128x128 tiles, k16 chunks, 256 threads = 8 warps (4m x 2n).
// qkv_mode 1: N=2304, scatter epilogue -> g_q (fp32) / g_k / g_v (fp16, v^T)
// qkv_mode 0: N=768, C = acc + bias (fp32)
// ---------------------------------------------------------------------------
#define ASTP 12                 // A row stride (floats): 32B data + 16B pad
#define BST  68                 // B row stride (floats): 256B data + 16B pad
#define A_STAGE_P (128 * ASTP)
#define B_STAGE_P (16 * BST)

__global__ void __launch_bounds__(256)
gemm_f16_kernel(const __half* __restrict__ Ah_g,
                const __half* __restrict__ Bh_g,
                const float* __restrict__ bias,
                float* __restrict__ C,
                int N, int K, int qkv_mode)
{
    extern __shared__ float gsm[];
    float* As  = gsm;                       // 2 x 128 x ASTP
    float* Bhs = As + 2 * A_STAGE_P;        // 2 x 16 x BST

    const int bx = blockIdx.x, by = blockIdx.y;
    const int t  = threadIdx.x;
    const int lane = t & 31, w = t >> 5;
    const int r = lane >> 2, c = lane & 3;
    const int wm = w >> 1, wn = w & 1;
    const int m0 = by * 128, n0 = bx * 128;
    const int mw = wm * 32,  nw = wn * 64;

    const int aRow  = (lane & 7) + ((lane >> 3) & 1) * 8;
    const int aColB = (lane >> 4) * 16;
    const int bRow  = (lane & 7) + ((lane >> 3) & 1) * 8;
    const int bColB = ((lane >> 4) & 1) * 16;

    const int am  = t >> 1;
    const int akh = (t & 1);
    const int bk  = t >> 4;
    const int bn4 = t & 15;

    const __half* Ag = Ah_g + (m0 + am) * K + akh * 8;
    const __half* Bg = Bh_g + n0 + bn4 * 4;

    const uint32_t as_b  = (uint32_t)__cvta_generic_to_shared(As);
    const uint32_t bhs_b = (uint32_t)__cvta_generic_to_shared(Bhs);

    uint4 a4;
    uint2 b4[2];
    float acc[2][8][4];
#pragma unroll
    for (int mg = 0; mg < 2; mg++)
#pragma unroll
        for (int ng = 0; ng < 8; ng++)
#pragma unroll
            for (int j = 0; j < 4; j++) acc[mg][ng][j] = 0.f;

    const int nk = K / 16;

    #define F16_LDG(i) do {                                              \
        const int kg_ = (i) * 16;                                        \
        a4 = *(const uint4*)(Ag + kg_);                                  \
        const __half* bp_ = Bg + (int64_t)(kg_ + bk) * N;                \
        b4[0] = *(const uint2*)(bp_);                                    \
        b4[1] = *(const uint2*)(bp_ + 64);                               \
    } while (0)

    #define F16_STS(s) do {                                              \
        float* as = As + (s) * A_STAGE_P;                                \
        float* bh = Bhs + (s) * B_STAGE_P;                               \
        *(uint4*)&as[am * ASTP + akh * 4] = a4;                          \
        const int wo = bk * BST + bn4 * 2;                               \
        *(uint2*)&bh[wo]      = b4[0];                                   \
        *(uint2*)&bh[wo + 32] = b4[1];                                   \
    } while (0)

    F16_LDG(0);
    F16_STS(0);
    F16_LDG(1);
    __syncthreads();

    for (int i = 0; i < nk; i++) {
        const int s = i & 1;
        const uint32_t aB  = as_b  + (uint32_t)(s * A_STAGE_P * 4) + (mw + aRow) * 48 + aColB;
        const uint32_t bhB = bhs_b + (uint32_t)(s * B_STAGE_P * 4) + bRow * 272 + bColB;

        unsigned ah[2][4];
#pragma unroll
        for (int mg = 0; mg < 2; mg++)
            ldsm4(ah[mg], aB + (uint32_t)(mg * 16 * 48));
#pragma unroll
        for (int g = 0; g < 4; g++) {
            unsigned bh[4];
            ldsm4t(bh, bhB + (uint32_t)((nw + g * 16) * 2));
#pragma unroll
            for (int half = 0; half < 2; half++) {
                const unsigned b0 = bh[half * 2], b1 = bh[half * 2 + 1];
                const int ng = g * 2 + half;
#pragma unroll
                for (int mg = 0; mg < 2; mg++)
                    mma_f16(acc[mg][ng], ah[mg][0], ah[mg][1], ah[mg][2], ah[mg][3], b0, b1);
            }
        }

        if (i + 1 < nk) {
            F16_STS((i + 1) & 1);
            if (i + 2 < nk) F16_LDG(i + 2);
        }
        __syncthreads();
    }

    // ---- epilogue ----
#pragma unroll
    for (int mg = 0; mg < 2; mg++) {
        const int row0 = m0 + mw + mg * 16 + r;
        const int row1 = row0 + 8;
#pragma unroll
        for (int ng = 0; ng < 8; ng++) {
            const int col = n0 + nw + ng * 8 + 2 * c;
            const float bs0 = bias[col], bs1 = bias[col + 1];
            float v00 = acc[mg][ng][0] + bs0, v01 = acc[mg][ng][1] + bs1;
            float v10 = acc[mg][ng][2] + bs0, v11 = acc[mg][ng][3] + bs1;
            if (qkv_mode == 0) {
                *(float2*)&C[(int64_t)row0 * N + col] = make_float2(v00, v01);
                *(float2*)&C[(int64_t)row1 * N + col] = make_float2(v10, v11);
            } else {
                const int part = col / DIM;
                const int rest = col - part * DIM;
                const int head = rest >> 6;
                const int d0   = rest & 63;
                if (part == 0) {
                    *(float2*)&g_q[(head * NTOK + row0) * HD + d0] = make_float2(v00, v01);
                    *(float2*)&g_q[(head * NTOK + row1) * HD + d0] = make_float2(v10, v11);
                } else if (part == 1) {
                    *(__half2*)&g_k[(head * NTOK + row0) * HD + d0] = __floats2half2_rn(v00, v01);
                    *(__half2*)&g_k[(head * NTOK + row1) * HD + d0] = __floats2half2_rn(v10, v11);
                } else {
                    __half* vt = g_v + head * HD * NTOK;
                    vt[(d0    ) * NTOK + row0] = __float2half_rn(v00);
                    vt[(d0 + 1) * NTOK + row0] = __float2half_rn(v01);
                    vt[(d0    ) * NTOK + row1] = __float2half_rn(v10);
                    vt[(d0 + 1) * NTOK + row1] = __float2half_rn(v11);
                }
            }
        }
    }
}

// ---------------------------------------------------------------------------
// rel-pos dot products (fp32, both modes via blockIdx.z)
// ---------------------------------------------------------------------------
__global__ void relpos_kernel(const float* __restrict__ gq,
                              const float* __restrict__ relh,
                              const float* __restrict__ relw,
                              float* __restrict__ outh,
                              float* __restrict__ outw)
{
    __shared__ float qs[64][65];
    __shared__ float rp[64][65];

    const int fixed = blockIdx.x;
    const int head  = blockIdx.y;
    const int mode  = blockIdx.z;
    const int t     = threadIdx.x;
    const float* relpos = mode ? relw : relh;
    float* out = mode ? outw : outh;

    if (mode == 0) {
        const float* base = gq + (head * NTOK + fixed * 64) * HD;
        for (int e = t; e < 4096; e += 256) qs[e >> 6][e & 63] = base[e];
    } else {
        const float* base = gq + (head * NTOK + fixed) * HD;
        for (int e = t; e < 4096; e += 256) {
            int row = e >> 6, c = e & 63;
            qs[row][c] = base[row * (64 * HD) + c];
        }
    }
    for (int e = t; e < 4096; e += 256) {
        int k = e >> 6, c = e & 63;
        rp[k][c] = relpos[(fixed - k + 63) * HD + c];
    }
    __syncthreads();

    const int qi = t >> 2;
    const int k0 = (t & 3) << 4;

    float accv[16];
#pragma unroll
    for (int j = 0; j < 16; j++) accv[j] = 0.f;

    for (int d = 0; d < 64; d++) {
        float qv = qs[qi][d];
#pragma unroll
        for (int j = 0; j < 16; j++) accv[j] += qv * rp[k0 + j][d];
    }

    const int n = (mode == 0) ? (fixed * 64 + qi) : (qi * 64 + fixed);
    float* op = out + (head * NTOK + n) * HD + k0;
#pragma unroll
    for (int j = 0; j < 16; j++) op[j] = accv[j];
}

// ---------------------------------------------------------------------------
// Flash attention (round-9 best-known version): fixed-shift softmax, fp16 MMA,
// smem P, 3-stage cp.async, split-KV x3.  128 threads = 4 warps x 32 Q rows.
// ---------------------------------------------------------------------------
#define STRH      72
#define ROW_B     144
#define KV_TILE_B (64 * ROW_B)               // 9216 B per tile
#define PQ_B      (128 * ROW_B)              // 18432 B
#define FLASH_SMEM_B (6 * KV_TILE_B + PQ_B)  // 73728 B

__global__ void __launch_bounds__(128, 2)
flash_v9_kernel(const float* __restrict__ gq,
                const __half* __restrict__ gk,
                const __half* __restrict__ gvt,
                const float* __restrict__ grh,
                const float* __restrict__ grw,
                float* __restrict__ po,
                float* __restrict__ pl)
{
    extern __shared__ char smc[];
    char*   Ksc = smc;                        // 3 stages x 64 x 144B
    char*   Vsc = smc + 3 * KV_TILE_B;        // 3 stages x 64 x 144B
    __half* PQh = (__half*)(smc + 6 * KV_TILE_B);   // 128 x 72 halves (Q -> P)

    const int qt   = blockIdx.x;
    const int head = blockIdx.y;
    const int z    = blockIdx.z;      // KV third
    const int ktb  = (z == 0) ? 0 : (22 + 21 * (z - 1));   // 0, 22, 43
    const int nit  = (z == 0) ? 22 : 21;
    const int t    = threadIdx.x;
    const int lane = t & 31;
    const int w    = t >> 5;
    const int r    = lane >> 2;
    const int c    = lane & 3;
    const int mbase = w * 32;

    const float*  qb   = gq  + (head * NTOK + qt * 128) * HD;
    const __half* kb0  = gk  + head * NTOK * HD;
    const char*   vtb0 = (const char*)(gvt + head * HD * NTOK);
    const float*  rhb  = grh + (head * NTOK + qt * 128 + mbase) * HD;
    const float*  rwb  = grw + (head * NTOK + qt * 128 + mbase) * HD;

    const uint32_t ks_sm = (uint32_t)__cvta_generic_to_shared(Ksc);
    const uint32_t vs_sm = (uint32_t)__cvta_generic_to_shared(Vsc);
    const uint32_t pq_sm = (uint32_t)__cvta_generic_to_shared(PQh);

    #define LOAD_KV(st, kt) do {                                              \
        const char* kb_ = (const char*)(kb0 + (kt) * 64 * HD);                \
        const uint32_t kd_ = ks_sm + (uint32_t)((st) * KV_TILE_B);            \
        const uint32_t vd_ = vs_sm + (uint32_t)((st) * KV_TILE_B);            \
        _Pragma("unroll")                                                     \
        for (int i_ = 0; i_ < 4; i_++) {                                      \
            const int ch_ = t + i_ * 128;                                     \
            const int row_ = ch_ >> 3, co_ = (ch_ & 7) * 16;                  \
            cp16(kd_ + row_ * ROW_B + co_, kb_ + row_ * 128 + co_);           \
            cp16(vd_ + row_ * ROW_B + co_,                                    \
                 vtb0 + row_ * (NTOK * 2) + (kt) * 128 + co_);                \
        }                                                                     \
    } while (0)

    // prologue: prefetch tiles ktb, ktb+1
    LOAD_KV(0, ktb);     CP_COMMIT();
    LOAD_KV(1, ktb + 1); CP_COMMIT();

    // stage Q (scaled into log2 domain, fp16)
    const float qsc = QKSCALE * LOG2E;
    for (int e = t; e < 128 * 32; e += 128) {
        const int row = e >> 5, c2 = (e & 31) * 2;
        float2 v = *(const float2*)(qb + row * HD + c2);
        *(__half2*)(PQh + row * STRH + c2) = __floats2half2_rn(v.x * qsc, v.y * qsc);
    }
    __syncthreads();

    // Q fragments (persist)
    const uint32_t aBase = pq_sm + (uint32_t)((mbase + (lane & 15)) * ROW_B
                                              + (lane >> 4) * 16);
    unsigned qa[2][4][4];
#pragma unroll
    for (int mb = 0; mb < 2; mb++)
#pragma unroll
        for (int kk = 0; kk < 4; kk++)
            ldsm4(qa[mb][kk], aBase + (uint32_t)(mb * 16 * ROW_B + kk * 32));
    __syncwarp();

    // rw bias in log2 domain, packed fp16x2: [mb][rowgroup][n]
    __half2 rwh[2][2][8];
#pragma unroll
    for (int mb = 0; mb < 2; mb++)
#pragma unroll
        for (int rg = 0; rg < 2; rg++)
#pragma unroll
            for (int n = 0; n < 8; n++) {
                float2 v = *(const float2*)&rwb[(mb * 16 + rg * 8 + r) * HD + n * 8 + 2 * c];
                rwh[mb][rg][n] = __floats2half2_rn(v.x * LOG2E, v.y * LOG2E);
            }

    float O[2][8][4];
#pragma unroll
    for (int mb = 0; mb < 2; mb++)
#pragma unroll
        for (int n = 0; n < 8; n++)
#pragma unroll
            for (int j = 0; j < 4; j++) O[mb][n][j] = 0.f;
    float l_[2][2] = {{0.f, 0.f}, {0.f, 0.f}};

    for (int it = 0; it < nit; it++) {
        const int kt = ktb + it;
        const int s  = it % 3;

        asm volatile("cp.async.wait_group 1;\n");
        __syncthreads();   // tile kt ready; all warps done with stage (it+2)%3

        if (it + 2 < nit) LOAD_KV((it + 2) % 3, kt + 2);
        CP_COMMIT();

        // rh bias (log2 domain, with -M0 shift folded in)
        float rh[2][2];
#pragma unroll
        for (int mb = 0; mb < 2; mb++) {
            rh[mb][0] = fmaf(__ldg(&rhb[(mb * 16 + r) * HD + kt]),     LOG2E, -M0SHIFT);
            rh[mb][1] = fmaf(__ldg(&rhb[(mb * 16 + 8 + r) * HD + kt]), LOG2E, -M0SHIFT);
        }

        const uint32_t kS = ks_sm + (uint32_t)(s * KV_TILE_B)
                              + (lane & 15) * ROW_B + (lane >> 4) * 16;
        const uint32_t vS = vs_sm + (uint32_t)(s * KV_TILE_B)
                              + (lane & 15) * ROW_B + (lane >> 4) * 16;

        // ---- S = Q K^T over full 64 keys ----
        float S[2][8][4];
#pragma unroll
        for (int mb = 0; mb < 2; mb++)
#pragma unroll
            for (int n = 0; n < 8; n++)
#pragma unroll
                for (int j = 0; j < 4; j++) S[mb][n][j] = 0.f;

#pragma unroll
        for (int kk = 0; kk < 4; kk++) {
#pragma unroll
            for (int g = 0; g < 4; g++) {     // 4 n16 key groups
                unsigned bb[4];
                ldsm4(bb, kS + (uint32_t)(g * 16 * ROW_B + kk * 32));
                mma_f16(S[0][g*2],   qa[0][kk][0], qa[0][kk][1], qa[0][kk][2], qa[0][kk][3], bb[0], bb[2]);
                mma_f16(S[0][g*2+1], qa[0][kk][0], qa[0][kk][1], qa[0][kk][2], qa[0][kk][3], bb[1], bb[3]);
                mma_f16(S[1][g*2],   qa[1][kk][0], qa[1][kk][1], qa[1][kk][2], qa[1][kk][3], bb[0], bb[2]);
                mma_f16(S[1][g*2+1], qa[1][kk][0], qa[1][kk][1], qa[1][kk][2], qa[1][kk][3], bb[1], bb[3]);
            }
        }

        // ---- fixed-shift softmax: p = 2^(S + rh' + rw') ----
#pragma unroll
        for (int mb = 0; mb < 2; mb++) {
            const float a0 = rh[mb][0];
            const float a1 = rh[mb][1];
            __half* prow0 = PQh + (mbase + mb * 16 + r) * STRH + 2 * c;
            __half* prow1 = prow0 + 8 * STRH;
            float s0 = 0.f, s1 = 0.f;
#pragma unroll
            for (int n = 0; n < 8; n++) {
                float2 w0 = __half22float2(rwh[mb][0][n]);
                float2 w1 = __half22float2(rwh[mb][1][n]);
                float p0 = ex2f(S[mb][n][0] + a0 + w0.x);
                float p1 = ex2f(S[mb][n][1] + a0 + w0.y);
                float p2 = ex2f(S[mb][n][2] + a1 + w1.x);
                float p3 = ex2f(S[mb][n][3] + a1 + w1.y);
                s0 += p0 + p1;  s1 += p2 + p3;
                *(__half2*)(prow0 + n * 8) = __floats2half2_rn(p0, p1);
                *(__half2*)(prow1 + n * 8) = __floats2half2_rn(p2, p3);
            }
            l_[mb][0] += s0;  l_[mb][1] += s1;
        }
        __syncwarp();   // P rows warp-private

        // ---- O += P V (64 keys = 4 k16 steps) ----
#pragma unroll
        for (int kk2 = 0; kk2 < 4; kk2++) {
            unsigned pa[2][4];
            ldsm4(pa[0], aBase + (uint32_t)(kk2 * 32));
            ldsm4(pa[1], aBase + (uint32_t)(16 * ROW_B + kk2 * 32));
#pragma unroll
            for (int p = 0; p < 4; p++) {      // d16 groups
                unsigned vv[4];
                ldsm4(vv, vS + (uint32_t)(p * 16 * ROW_B + kk2 * 32));
                mma_f16(O[0][p*2],   pa[0][0], pa[0][1], pa[0][2], pa[0][3], vv[0], vv[2]);
                mma_f16(O[0][p*2+1], pa[0][0], pa[0][1], pa[0][2], pa[0][3], vv[1], vv[3]);
                mma_f16(O[1][p*2],   pa[1][0], pa[1][1], pa[1][2], pa[1][3], vv[0], vv[2]);
                mma_f16(O[1][p*2+1], pa[1][0], pa[1][1], pa[1][2], pa[1][3], vv[1], vv[3]);
            }
        }
        __syncwarp();   // P reads done before next iter's stores
    }

    // ---- epilogue: reduce l across the 4 lanes of each row, store partials ----
#pragma unroll
    for (int mb = 0; mb < 2; mb++)
#pragma unroll
        for (int rg = 0; rg < 2; rg++) {
            float l = l_[mb][rg];
            l += __shfl_xor_sync(0xffffffffu, l, 1);
            l += __shfl_xor_sync(0xffffffffu, l, 2);
            l_[mb][rg] = l;
        }

    const int pz = z * NH * NTOK + head * NTOK;
#pragma unroll
    for (int mb = 0; mb < 2; mb++) {
        const int row0 = qt * 128 + mbase + mb * 16 + r;
        const int row1 = row0 + 8;
        if (c == 0) {
            pl[pz + row0] = l_[mb][0];
            pl[pz + row1] = l_[mb][1];
        }
#pragma unroll
        for (int n = 0; n < 8; n++) {
            const int col = n * 8 + 2 * c;
            *(float2*)&po[(pz + row0) * HD + col] = make_float2(O[mb][n][0], O[mb][n][1]);
            *(float2*)&po[(pz + row1) * HD + col] = make_float2(O[mb][n][2], O[mb][n][3]);
        }
    }
}

// ---------------------------------------------------------------------------
// merge the three KV-third partials -> g_aoh (fp16, feeds proj GEMM)
// ---------------------------------------------------------------------------
__global__ void merge_kernel(const float* __restrict__ po,
                             const float* __restrict__ pl,
                             __half* __restrict__ aoh)
{
    const int gid = blockIdx.x * 256 + threadIdx.x;
    const int dp  = (gid & 7) * 8;
    const int hr  = gid >> 3;
    const int head = hr >> 12, row = hr & 4095;
    const int S = NH * NTOK;

    const float inv = 1.0f / (pl[hr] + pl[S + hr] + pl[2 * S + hr]);

    const float* o0 = po + (size_t)hr * HD + dp;
    const float* o1 = po + (size_t)(S + hr) * HD + dp;
    const float* o2 = po + (size_t)(2 * S + hr) * HD + dp;
    __half* dst = aoh + row * DIM + head * HD + dp;

    uint4 outw;
    unsigned* ow = (unsigned*)&outw;
#pragma unroll
    for (int j = 0; j < 8; j += 2) {
        float x = (o0[j]     + o1[j]     + o2[j])     * inv;
        float y = (o0[j + 1] + o1[j + 1] + o2[j + 1]) * inv;
        __half2 h = __floats2half2_rn(x, y);
        ow[j >> 1] = *(unsigned*)&h;
    }
    *(uint4*)dst = outw;
}

// ---------------------------------------------------------------------------
extern "C" void kernel_launch(void* const* d_in, const int* in_sizes, int n_in,
                              void* d_out, int out_size)
{
    const float* x        = (const float*)d_in[0];
    const float* w_qkv    = (const float*)d_in[1];
    const float* b_qkv    = (const float*)d_in[2];
    const float* w_proj   = (const float*)d_in[3];
    const float* b_proj   = (const float*)d_in[4];
    const float* rel_h    = (const float*)d_in[5];
    const float* rel_w    = (const float*)d_in[6];
    float* out = (float*)d_out;

    float *gq, *grh, *grw, *gpo, *gpl;
    __half *gk, *gv, *gxh, *gwqh, *gwph, *gaoh;
    cudaGetSymbolAddress((void**)&gq,   g_q);
    cudaGetSymbolAddress((void**)&gk,   g_k);
    cudaGetSymbolAddress((void**)&gv,   g_v);
    cudaGetSymbolAddress((void**)&grh,  g_relh);
    cudaGetSymbolAddress((void**)&grw,  g_relw);
    cudaGetSymbolAddress((void**)&gpo,  g_po);
    cudaGetSymbolAddress((void**)&gpl,  g_pl);
    cudaGetSymbolAddress((void**)&gxh,  g_xh);
    cudaGetSymbolAddress((void**)&gwqh, g_wqh);
    cudaGetSymbolAddress((void**)&gwph, g_wph);
    cudaGetSymbolAddress((void**)&gaoh, g_aoh);

    // 0) convert operands to fp16
    conv_half_kernel<<<(NTOK * DIM / 4 + 255) / 256, 256>>>(x, gxh, NTOK * DIM / 4);
    conv_half_kernel<<<(DIM * 3 * DIM / 4 + 255) / 256, 256>>>(w_qkv, gwqh, DIM * 3 * DIM / 4);
    conv_half_kernel<<<(DIM * DIM / 4 + 255) / 256, 256>>>(w_proj, gwph, DIM * DIM / 4);

    static const int GEMM_SMEM = (2 * A_STAGE_P + 2 * B_STAGE_P) * (int)sizeof(float);  // 20,992 B
    cudaFuncSetAttribute(gemm_f16_kernel,
                         cudaFuncAttributeMaxDynamicSharedMemorySize, GEMM_SMEM);

    // 1) QKV GEMM (fp16 x1), scatter q (fp32) / k / v^T (fp16)
    gemm_f16_kernel<<<dim3(3 * DIM / 128, NTOK / 128), 256, GEMM_SMEM>>>(
        gxh, gwqh, b_qkv, nullptr, 3 * DIM, DIM, 1);

    // 2) rel_h / rel_w (fused)
    relpos_kernel<<<dim3(GRID_HW, NH, 2), 256>>>(gq, rel_h, rel_w, grh, grw);

    // 3) flash attention (round-9 best, split-KV x3)
    cudaFuncSetAttribute(flash_v9_kernel,
                         cudaFuncAttributeMaxDynamicSharedMemorySize, FLASH_SMEM_B);
    flash_v9_kernel<<<dim3(NTOK / 128, NH, NSPLIT), 128, FLASH_SMEM_B>>>(
        gq, gk, gv, grh, grw, gpo, gpl);

    // 4) merge partials -> fp16 ao
    merge_kernel<<<NH * NTOK * 8 / 256, 256>>>(gpo, gpl, gaoh);

    // 5) output projection (fp16 x1)
    gemm_f16_kernel<<<dim3(DIM / 128, NTOK / 128), 256, GEMM_SMEM>>>(
        gaoh, gwph, b_proj, out, DIM, DIM, 0);
}

// round 12
// speedup vs baseline: 1.2023x; 1.0602x over previous
#include <cuda_runtime.h>
#include <cuda_fp16.h>
#include <cuda_bf16.h>
#include <cstdint>

// Problem constants
#define NTOK   4096      // 64*64 tokens
#define DIM    768
#define NH     12
#define HD     64
#define GRID_HW 64
#define QKSCALE 0.125f   // 64^-0.5
#define LOG2E   1.44269504f
#define M0SHIFT 5.77078016f   // 4.0 * log2(e)
#define NSPLIT 3              // split-KV factor

// ---------------- scratch (device globals; no allocation allowed) ----------
__device__ float  g_q[NH * NTOK * HD];                 // fp32 q, [head][tok][d]
__device__ __align__(16) __half g_k[NH * NTOK * HD];   // fp16 k, [head][tok][d]
__device__ __align__(16) __half g_v[NH * HD * NTOK];   // fp16 v TRANSPOSED [head][d][tok]
__device__ float g_relh[NH * NTOK * HD];               // [head][n][kh]
__device__ float g_relw[NH * NTOK * HD];               // [head][n][kw]
__device__ float g_po[NSPLIT * NH * NTOK * HD];        // split-KV unnormalized O
__device__ float g_pl[NSPLIT * NH * NTOK];             // split-KV partial l
// fp16 GEMM operands
__device__ __align__(16) __half g_xh[NTOK * DIM];      // x fp16
__device__ __align__(16) __half g_wqh[DIM * 3 * DIM];  // w_qkv fp16
__device__ __align__(16) __half g_wph[DIM * DIM];      // w_proj fp16
__device__ __align__(16) __half g_aoh[NTOK * DIM];     // attention out fp16

// ---------------------------------------------------------------------------
// helpers
// ---------------------------------------------------------------------------
__device__ __forceinline__ __half2 ex2h2(__half2 x) {
    __half2 y;
    asm("ex2.approx.f16x2 %0, %1;"
        : "=r"(*reinterpret_cast<unsigned*>(&y))
        : "r"(*reinterpret_cast<unsigned*>(&x)));
    return y;
}

__device__ __forceinline__ void mma_f16(float c[4],
                                        unsigned a0, unsigned a1, unsigned a2, unsigned a3,
                                        unsigned b0, unsigned b1) {
    asm volatile(
        "mma.sync.aligned.m16n8k16.row.col.f32.f16.f16.f32 "
        "{%0,%1,%2,%3}, {%4,%5,%6,%7}, {%8,%9}, {%0,%1,%2,%3};\n"
        : "+f"(c[0]), "+f"(c[1]), "+f"(c[2]), "+f"(c[3])
        : "r"(a0), "r"(a1), "r"(a2), "r"(a3), "r"(b0), "r"(b1));
}

__device__ __forceinline__ void ldsm4(unsigned* d, uint32_t addr) {
    asm volatile("ldmatrix.sync.aligned.m8n8.x4.shared.b16 {%0,%1,%2,%3}, [%4];\n"
                 : "=r"(d[0]), "=r"(d[1]), "=r"(d[2]), "=r"(d[3]) : "r"(addr));
}

__device__ __forceinline__ void ldsm4t(unsigned* d, uint32_t addr) {
    asm volatile("ldmatrix.sync.aligned.m8n8.x4.trans.shared.b16 {%0,%1,%2,%3}, [%4];\n"
                 : "=r"(d[0]), "=r"(d[1]), "=r"(d[2]), "=r"(d[3]) : "r"(addr));
}

__device__ __forceinline__ void cp16(uint32_t dst, const void* src) {
    asm volatile("cp.async.cg.shared.global [%0], [%1], 16;\n" :: "r"(dst), "l"(src));
}
#define CP_COMMIT() asm volatile("cp.async.commit_group;\n")

// ---------------------------------------------------------------------------
// conversion kernel (fp32 -> fp16), vectorized
// ---------------------------------------------------------------------------
__global__ void conv_half_kernel(const float* __restrict__ in,
                                 __half* __restrict__ out, int n4)
{
    const int i = blockIdx.x * 256 + threadIdx.x;
    if (i >= n4) return;
    float4 v = ((const float4*)in)[i];
    __half2 h0 = __floats2half2_rn(v.x, v.y);
    __half2 h1 = __floats2half2_rn(v.z, v.w);
    ((uint2*)out)[i] = make_uint2(*(unsigned*)&h0, *(unsigned*)&h1);
}

// ---------------------------------------------------------------------------
// fp16 x1 GEMM (unchanged from round 11)
// ---------------------------------------------------------------------------
#define ASTP 12
#define BST  68
#define A_STAGE_P (128 * ASTP)
#define B_STAGE_P (16 * BST)

__global__ void __launch_bounds__(256)
gemm_f16_kernel(const __half* __restrict__ Ah_g,
                const __half* __restrict__ Bh_g,
                const float* __restrict__ bias,
                float* __restrict__ C,
                int N, int K, int qkv_mode)
{
    extern __shared__ float gsm[];
    float* As  = gsm;
    float* Bhs = As + 2 * A_STAGE_P;

    const int bx = blockIdx.x, by = blockIdx.y;
    const int t  = threadIdx.x;
    const int lane = t & 31, w = t >> 5;
    const int r = lane >> 2, c = lane & 3;
    const int wm = w >> 1, wn = w & 1;
    const int m0 = by * 128, n0 = bx * 128;
    const int mw = wm * 32,  nw = wn * 64;

    const int aRow  = (lane & 7) + ((lane >> 3) & 1) * 8;
    const int aColB = (lane >> 4) * 16;
    const int bRow  = (lane & 7) + ((lane >> 3) & 1) * 8;
    const int bColB = ((lane >> 4) & 1) * 16;

    const int am  = t >> 1;
    const int akh = (t & 1);
    const int bk  = t >> 4;
    const int bn4 = t & 15;

    const __half* Ag = Ah_g + (m0 + am) * K + akh * 8;
    const __half* Bg = Bh_g + n0 + bn4 * 4;

    const uint32_t as_b  = (uint32_t)__cvta_generic_to_shared(As);
    const uint32_t bhs_b = (uint32_t)__cvta_generic_to_shared(Bhs);

    uint4 a4;
    uint2 b4[2];
    float acc[2][8][4];
#pragma unroll
    for (int mg = 0; mg < 2; mg++)
#pragma unroll
        for (int ng = 0; ng < 8; ng++)
#pragma unroll
            for (int j = 0; j < 4; j++) acc[mg][ng][j] = 0.f;

    const int nk = K / 16;

    #define F16_LDG(i) do {                                              \
        const int kg_ = (i) * 16;                                        \
        a4 = *(const uint4*)(Ag + kg_);                                  \
        const __half* bp_ = Bg + (int64_t)(kg_ + bk) * N;                \
        b4[0] = *(const uint2*)(bp_);                                    \
        b4[1] = *(const uint2*)(bp_ + 64);                               \
    } while (0)

    #define F16_STS(s) do {                                              \
        float* as = As + (s) * A_STAGE_P;                                \
        float* bh = Bhs + (s) * B_STAGE_P;                               \
        *(uint4*)&as[am * ASTP + akh * 4] = a4;                          \
        const int wo = bk * BST + bn4 * 2;                               \
        *(uint2*)&bh[wo]      = b4[0];                                   \
        *(uint2*)&bh[wo + 32] = b4[1];                                   \
    } while (0)

    F16_LDG(0);
    F16_STS(0);
    F16_LDG(1);
    __syncthreads();

    for (int i = 0; i < nk; i++) {
        const int s = i & 1;
        const uint32_t aB  = as_b  + (uint32_t)(s * A_STAGE_P * 4) + (mw + aRow) * 48 + aColB;
        const uint32_t bhB = bhs_b + (uint32_t)(s * B_STAGE_P * 4) + bRow * 272 + bColB;

        unsigned ah[2][4];
#pragma unroll
        for (int mg = 0; mg < 2; mg++)
            ldsm4(ah[mg], aB + (uint32_t)(mg * 16 * 48));
#pragma unroll
        for (int g = 0; g < 4; g++) {
            unsigned bh[4];
            ldsm4t(bh, bhB + (uint32_t)((nw + g * 16) * 2));
#pragma unroll
            for (int half = 0; half < 2; half++) {
                const unsigned b0 = bh[half * 2], b1 = bh[half * 2 + 1];
                const int ng = g * 2 + half;
#pragma unroll
                for (int mg = 0; mg < 2; mg++)
                    mma_f16(acc[mg][ng], ah[mg][0], ah[mg][1], ah[mg][2], ah[mg][3], b0, b1);
            }
        }

        if (i + 1 < nk) {
            F16_STS((i + 1) & 1);
            if (i + 2 < nk) F16_LDG(i + 2);
        }
        __syncthreads();
    }

    // ---- epilogue ----
#pragma unroll
    for (int mg = 0; mg < 2; mg++) {
        const int row0 = m0 + mw + mg * 16 + r;
        const int row1 = row0 + 8;
#pragma unroll
        for (int ng = 0; ng < 8; ng++) {
            const int col = n0 + nw + ng * 8 + 2 * c;
            const float bs0 = bias[col], bs1 = bias[col + 1];
            float v00 = acc[mg][ng][0] + bs0, v01 = acc[mg][ng][1] + bs1;
            float v10 = acc[mg][ng][2] + bs0, v11 = acc[mg][ng][3] + bs1;
            if (qkv_mode == 0) {
                *(float2*)&C[(int64_t)row0 * N + col] = make_float2(v00, v01);
                *(float2*)&C[(int64_t)row1 * N + col] = make_float2(v10, v11);
            } else {
                const int part = col / DIM;
                const int rest = col - part * DIM;
                const int head = rest >> 6;
                const int d0   = rest & 63;
                if (part == 0) {
                    *(float2*)&g_q[(head * NTOK + row0) * HD + d0] = make_float2(v00, v01);
                    *(float2*)&g_q[(head * NTOK + row1) * HD + d0] = make_float2(v10, v11);
                } else if (part == 1) {
                    *(__half2*)&g_k[(head * NTOK + row0) * HD + d0] = __floats2half2_rn(v00, v01);
                    *(__half2*)&g_k[(head * NTOK + row1) * HD + d0] = __floats2half2_rn(v10, v11);
                } else {
                    __half* vt = g_v + head * HD * NTOK;
                    vt[(d0    ) * NTOK + row0] = __float2half_rn(v00);
                    vt[(d0 + 1) * NTOK + row0] = __float2half_rn(v01);
                    vt[(d0    ) * NTOK + row1] = __float2half_rn(v10);
                    vt[(d0 + 1) * NTOK + row1] = __float2half_rn(v11);
                }
            }
        }
    }
}

// ---------------------------------------------------------------------------
// rel-pos dot products (fp32, both modes via blockIdx.z) — unchanged
// ---------------------------------------------------------------------------
__global__ void relpos_kernel(const float* __restrict__ gq,
                              const float* __restrict__ relh,
                              const float* __restrict__ relw,
                              float* __restrict__ outh,
                              float* __restrict__ outw)
{
    __shared__ float qs[64][65];
    __shared__ float rp[64][65];

    const int fixed = blockIdx.x;
    const int head  = blockIdx.y;
    const int mode  = blockIdx.z;
    const int t     = threadIdx.x;
    const float* relpos = mode ? relw : relh;
    float* out = mode ? outw : outh;

    if (mode == 0) {
        const float* base = gq + (head * NTOK + fixed * 64) * HD;
        for (int e = t; e < 4096; e += 256) qs[e >> 6][e & 63] = base[e];
    } else {
        const float* base = gq + (head * NTOK + fixed) * HD;
        for (int e = t; e < 4096; e += 256) {
            int row = e >> 6, c = e & 63;
            qs[row][c] = base[row * (64 * HD) + c];
        }
    }
    for (int e = t; e < 4096; e += 256) {
        int k = e >> 6, c = e & 63;
        rp[k][c] = relpos[(fixed - k + 63) * HD + c];
    }
    __syncthreads();

    const int qi = t >> 2;
    const int k0 = (t & 3) << 4;

    float accv[16];
#pragma unroll
    for (int j = 0; j < 16; j++) accv[j] = 0.f;

    for (int d = 0; d < 64; d++) {
        float qv = qs[qi][d];
#pragma unroll
        for (int j = 0; j < 16; j++) accv[j] += qv * rp[k0 + j][d];
    }

    const int n = (mode == 0) ? (fixed * 64 + qi) : (qi * 64 + fixed);
    float* op = out + (head * NTOK + n) * HD + k0;
#pragma unroll
    for (int j = 0; j < 16; j++) op[j] = accv[j];
}

// ---------------------------------------------------------------------------
// Flash attention v12: f16x2 softmax (ex2.approx.f16x2), l via ones-MMA,
// fixed-shift softmax, smem P, 3-stage cp.async, split-KV x3.
// 128 threads = 4 warps x 32 Q rows.
// ---------------------------------------------------------------------------
#define STRH      72
#define ROW_B     144
#define KV_TILE_B (64 * ROW_B)               // 9216 B per tile
#define PQ_B      (128 * ROW_B)              // 18432 B
#define FLASH_SMEM_B (6 * KV_TILE_B + PQ_B)  // 73728 B
#define ONESH2 0x3C003C00u                    // half2(1,1)

__global__ void __launch_bounds__(128, 2)
flash_v12_kernel(const float* __restrict__ gq,
                 const __half* __restrict__ gk,
                 const __half* __restrict__ gvt,
                 const float* __restrict__ grh,
                 const float* __restrict__ grw,
                 float* __restrict__ po,
                 float* __restrict__ pl)
{
    extern __shared__ char smc[];
    char*   Ksc = smc;                        // 3 stages x 64 x 144B
    char*   Vsc = smc + 3 * KV_TILE_B;        // 3 stages x 64 x 144B
    __half* PQh = (__half*)(smc + 6 * KV_TILE_B);   // 128 x 72 halves (Q -> P)

    const int qt   = blockIdx.x;
    const int head = blockIdx.y;
    const int z    = blockIdx.z;      // KV third
    const int ktb  = (z == 0) ? 0 : (22 + 21 * (z - 1));   // 0, 22, 43
    const int nit  = (z == 0) ? 22 : 21;
    const int t    = threadIdx.x;
    const int lane = t & 31;
    const int w    = t >> 5;
    const int r    = lane >> 2;
    const int c    = lane & 3;
    const int mbase = w * 32;

    const float*  qb   = gq  + (head * NTOK + qt * 128) * HD;
    const __half* kb0  = gk  + head * NTOK * HD;
    const char*   vtb0 = (const char*)(gvt + head * HD * NTOK);
    const float*  rhb  = grh + (head * NTOK + qt * 128 + mbase) * HD;
    const float*  rwb  = grw + (head * NTOK + qt * 128 + mbase) * HD;

    const uint32_t ks_sm = (uint32_t)__cvta_generic_to_shared(Ksc);
    const uint32_t vs_sm = (uint32_t)__cvta_generic_to_shared(Vsc);
    const uint32_t pq_sm = (uint32_t)__cvta_generic_to_shared(PQh);

    #define LOAD_KV(st, kt) do {                                              \
        const char* kb_ = (const char*)(kb0 + (kt) * 64 * HD);                \
        const uint32_t kd_ = ks_sm + (uint32_t)((st) * KV_TILE_B);            \
        const uint32_t vd_ = vs_sm + (uint32_t)((st) * KV_TILE_B);            \
        _Pragma("unroll")                                                     \
        for (int i_ = 0; i_ < 4; i_++) {                                      \
            const int ch_ = t + i_ * 128;                                     \
            const int row_ = ch_ >> 3, co_ = (ch_ & 7) * 16;                  \
            cp16(kd_ + row_ * ROW_B + co_, kb_ + row_ * 128 + co_);           \
            cp16(vd_ + row_ * ROW_B + co_,                                    \
                 vtb0 + row_ * (NTOK * 2) + (kt) * 128 + co_);                \
        }                                                                     \
    } while (0)

    // prologue: prefetch tiles ktb, ktb+1
    LOAD_KV(0, ktb);     CP_COMMIT();
    LOAD_KV(1, ktb + 1); CP_COMMIT();

    // stage Q (scaled into log2 domain, fp16)
    const float qsc = QKSCALE * LOG2E;
    for (int e = t; e < 128 * 32; e += 128) {
        const int row = e >> 5, c2 = (e & 31) * 2;
        float2 v = *(const float2*)(qb + row * HD + c2);
        *(__half2*)(PQh + row * STRH + c2) = __floats2half2_rn(v.x * qsc, v.y * qsc);
    }
    __syncthreads();

    // Q fragments (persist)
    const uint32_t aBase = pq_sm + (uint32_t)((mbase + (lane & 15)) * ROW_B
                                              + (lane >> 4) * 16);
    unsigned qa[2][4][4];
#pragma unroll
    for (int mb = 0; mb < 2; mb++)
#pragma unroll
        for (int kk = 0; kk < 4; kk++)
            ldsm4(qa[mb][kk], aBase + (uint32_t)(mb * 16 * ROW_B + kk * 32));
    __syncwarp();

    // rw bias in log2 domain, packed fp16x2: [mb][rowgroup][n]
    __half2 rwh[2][2][8];
#pragma unroll
    for (int mb = 0; mb < 2; mb++)
#pragma unroll
        for (int rg = 0; rg < 2; rg++)
#pragma unroll
            for (int n = 0; n < 8; n++) {
                float2 v = *(const float2*)&rwb[(mb * 16 + rg * 8 + r) * HD + n * 8 + 2 * c];
                rwh[mb][rg][n] = __floats2half2_rn(v.x * LOG2E, v.y * LOG2E);
            }

    float O[2][8][4];
#pragma unroll
    for (int mb = 0; mb < 2; mb++)
#pragma unroll
        for (int n = 0; n < 8; n++)
#pragma unroll
            for (int j = 0; j < 4; j++) O[mb][n][j] = 0.f;
    float lacc[2][4];   // row-sum accumulators via ones-MMA: [mb][cfrag]
#pragma unroll
    for (int mb = 0; mb < 2; mb++)
#pragma unroll
        for (int j = 0; j < 4; j++) lacc[mb][j] = 0.f;

    for (int it = 0; it < nit; it++) {
        const int kt = ktb + it;
        const int s  = it % 3;

        asm volatile("cp.async.wait_group 1;\n");
        __syncthreads();   // tile kt ready; all warps done with stage (it+2)%3

        if (it + 2 < nit) LOAD_KV((it + 2) % 3, kt + 2);
        CP_COMMIT();

        // rh bias (log2 domain, with -M0 shift folded in)
        float rh[2][2];
#pragma unroll
        for (int mb = 0; mb < 2; mb++) {
            rh[mb][0] = fmaf(__ldg(&rhb[(mb * 16 + r) * HD + kt]),     LOG2E, -M0SHIFT);
            rh[mb][1] = fmaf(__ldg(&rhb[(mb * 16 + 8 + r) * HD + kt]), LOG2E, -M0SHIFT);
        }

        const uint32_t kS = ks_sm + (uint32_t)(s * KV_TILE_B)
                              + (lane & 15) * ROW_B + (lane >> 4) * 16;
        const uint32_t vS = vs_sm + (uint32_t)(s * KV_TILE_B)
                              + (lane & 15) * ROW_B + (lane >> 4) * 16;

        // ---- S = Q K^T over full 64 keys ----
        float S[2][8][4];
#pragma unroll
        for (int mb = 0; mb < 2; mb++)
#pragma unroll
            for (int n = 0; n < 8; n++)
#pragma unroll
                for (int j = 0; j < 4; j++) S[mb][n][j] = 0.f;

#pragma unroll
        for (int kk = 0; kk < 4; kk++) {
#pragma unroll
            for (int g = 0; g < 4; g++) {     // 4 n16 key groups
                unsigned bb[4];
                ldsm4(bb, kS + (uint32_t)(g * 16 * ROW_B + kk * 32));
                mma_f16(S[0][g*2],   qa[0][kk][0], qa[0][kk][1], qa[0][kk][2], qa[0][kk][3], bb[0], bb[2]);
                mma_f16(S[0][g*2+1], qa[0][kk][0], qa[0][kk][1], qa[0][kk][2], qa[0][kk][3], bb[1], bb[3]);
                mma_f16(S[1][g*2],   qa[1][kk][0], qa[1][kk][1], qa[1][kk][2], qa[1][kk][3], bb[0], bb[2]);
                mma_f16(S[1][g*2+1], qa[1][kk][0], qa[1][kk][1], qa[1][kk][2], qa[1][kk][3], bb[1], bb[3]);
            }
        }

        // ---- fixed-shift softmax: p = 2^(S + rh' + rw'), f16x2 exp ----
#pragma unroll
        for (int mb = 0; mb < 2; mb++) {
            const float a0 = rh[mb][0];
            const float a1 = rh[mb][1];
            __half* prow0 = PQh + (mbase + mb * 16 + r) * STRH + 2 * c;
            __half* prow1 = prow0 + 8 * STRH;
#pragma unroll
            for (int n = 0; n < 8; n++) {
                __half2 h01 = __floats2half2_rn(S[mb][n][0] + a0, S[mb][n][1] + a0);
                __half2 h23 = __floats2half2_rn(S[mb][n][2] + a1, S[mb][n][3] + a1);
                __half2 p01 = ex2h2(__hadd2(h01, rwh[mb][0][n]));
                __half2 p23 = ex2h2(__hadd2(h23, rwh[mb][1][n]));
                *(__half2*)(prow0 + n * 8) = p01;
                *(__half2*)(prow1 + n * 8) = p23;
            }
        }
        __syncwarp();   // P rows warp-private

        // ---- O += P V (64 keys = 4 k16 steps); l += P * ones ----
#pragma unroll
        for (int kk2 = 0; kk2 < 4; kk2++) {
            unsigned pa[2][4];
            ldsm4(pa[0], aBase + (uint32_t)(kk2 * 32));
            ldsm4(pa[1], aBase + (uint32_t)(16 * ROW_B + kk2 * 32));
            // row sums (every column of B is 1 -> each lane gets its row's sum)
            mma_f16(lacc[0], pa[0][0], pa[0][1], pa[0][2], pa[0][3], ONESH2, ONESH2);
            mma_f16(lacc[1], pa[1][0], pa[1][1], pa[1][2], pa[1][3], ONESH2, ONESH2);
#pragma unroll
            for (int p = 0; p < 4; p++) {      // d16 groups
                unsigned vv[4];
                ldsm4(vv, vS + (uint32_t)(p * 16 * ROW_B + kk2 * 32));
                mma_f16(O[0][p*2],   pa[0][0], pa[0][1], pa[0][2], pa[0][3], vv[0], vv[2]);
                mma_f16(O[0][p*2+1], pa[0][0], pa[0][1], pa[0][2], pa[0][3], vv[1], vv[3]);
                mma_f16(O[1][p*2],   pa[1][0], pa[1][1], pa[1][2], pa[1][3], vv[0], vv[2]);
                mma_f16(O[1][p*2+1], pa[1][0], pa[1][1], pa[1][2], pa[1][3], vv[1], vv[3]);
            }
        }
        __syncwarp();   // P reads done before next iter's stores
    }

    // ---- epilogue: lacc c0 = full row sum (row r), c2 = row r+8 ----
    const int pz = z * NH * NTOK + head * NTOK;
#pragma unroll
    for (int mb = 0; mb < 2; mb++) {
        const int row0 = qt * 128 + mbase + mb * 16 + r;
        const int row1 = row0 + 8;
        if (c == 0) {
            pl[pz + row0] = lacc[mb][0];
            pl[pz + row1] = lacc[mb][2];
        }
#pragma unroll
        for (int n = 0; n < 8; n++) {
            const int col = n * 8 + 2 * c;
            *(float2*)&po[(pz + row0) * HD + col] = make_float2(O[mb][n][0], O[mb][n][1]);
            *(float2*)&po[(pz + row1) * HD + col] = make_float2(O[mb][n][2], O[mb][n][3]);
        }
    }
}

// ---------------------------------------------------------------------------
// merge the three KV-third partials -> g_aoh (fp16, feeds proj GEMM)
// ---------------------------------------------------------------------------
__global__ void merge_kernel(const float* __restrict__ po,
                             const float* __restrict__ pl,
                             __half* __restrict__ aoh)
{
    const int gid = blockIdx.x * 256 + threadIdx.x;
    const int dp  = (gid & 7) * 8;
    const int hr  = gid >> 3;
    const int head = hr >> 12, row = hr & 4095;
    const int S = NH * NTOK;

    const float inv = 1.0f / (pl[hr] + pl[S + hr] + pl[2 * S + hr]);

    const float* o0 = po + (size_t)hr * HD + dp;
    const float* o1 = po + (size_t)(S + hr) * HD + dp;
    const float* o2 = po + (size_t)(2 * S + hr) * HD + dp;
    __half* dst = aoh + row * DIM + head * HD + dp;

    uint4 outw;
    unsigned* ow = (unsigned*)&outw;
#pragma unroll
    for (int j = 0; j < 8; j += 2) {
        float x = (o0[j]     + o1[j]     + o2[j])     * inv;
        float y = (o0[j + 1] + o1[j + 1] + o2[j + 1]) * inv;
        __half2 h = __floats2half2_rn(x, y);
        ow[j >> 1] = *(unsigned*)&h;
    }
    *(uint4*)dst = outw;
}

// ---------------------------------------------------------------------------
extern "C" void kernel_launch(void* const* d_in, const int* in_sizes, int n_in,
                              void* d_out, int out_size)
{
    const float* x        = (const float*)d_in[0];
    const float* w_qkv    = (const float*)d_in[1];
    const float* b_qkv    = (const float*)d_in[2];
    const float* w_proj   = (const float*)d_in[3];
    const float* b_proj   = (const float*)d_in[4];
    const float* rel_h    = (const float*)d_in[5];
    const float* rel_w    = (const float*)d_in[6];
    float* out = (float*)d_out;

    float *gq, *grh, *grw, *gpo, *gpl;
    __half *gk, *gv, *gxh, *gwqh, *gwph, *gaoh;
    cudaGetSymbolAddress((void**)&gq,   g_q);
    cudaGetSymbolAddress((void**)&gk,   g_k);
    cudaGetSymbolAddress((void**)&gv,   g_v);
    cudaGetSymbolAddress((void**)&grh,  g_relh);
    cudaGetSymbolAddress((void**)&grw,  g_relw);
    cudaGetSymbolAddress((void**)&gpo,  g_po);
    cudaGetSymbolAddress((void**)&gpl,  g_pl);
    cudaGetSymbolAddress((void**)&gxh,  g_xh);
    cudaGetSymbolAddress((void**)&gwqh, g_wqh);
    cudaGetSymbolAddress((void**)&gwph, g_wph);
    cudaGetSymbolAddress((void**)&gaoh, g_aoh);

    // 0) convert operands to fp16
    conv_half_kernel<<<(NTOK * DIM / 4 + 255) / 256, 256>>>(x, gxh, NTOK * DIM / 4);
    conv_half_kernel<<<(DIM * 3 * DIM / 4 + 255) / 256, 256>>>(w_qkv, gwqh, DIM * 3 * DIM / 4);
    conv_half_kernel<<<(DIM * DIM / 4 + 255) / 256, 256>>>(w_proj, gwph, DIM * DIM / 4);

    static const int GEMM_SMEM = (2 * A_STAGE_P + 2 * B_STAGE_P) * (int)sizeof(float);  // 20,992 B
    cudaFuncSetAttribute(gemm_f16_kernel,
                         cudaFuncAttributeMaxDynamicSharedMemorySize, GEMM_SMEM);

    // 1) QKV GEMM (fp16 x1), scatter q (fp32) / k / v^T (fp16)
    gemm_f16_kernel<<<dim3(3 * DIM / 128, NTOK / 128), 256, GEMM_SMEM>>>(
        gxh, gwqh, b_qkv, nullptr, 3 * DIM, DIM, 1);

    // 2) rel_h / rel_w (fused)
    relpos_kernel<<<dim3(GRID_HW, NH, 2), 256>>>(gq, rel_h, rel_w, grh, grw);

    // 3) flash attention v12 (f16x2 softmax, l via ones-MMA, split-KV x3)
    cudaFuncSetAttribute(flash_v12_kernel,
                         cudaFuncAttributeMaxDynamicSharedMemorySize, FLASH_SMEM_B);
    flash_v12_kernel<<<dim3(NTOK / 128, NH, NSPLIT), 128, FLASH_SMEM_B>>>(
        gq, gk, gv, grh, grw, gpo, gpl);

    // 4) merge partials -> fp16 ao
    merge_kernel<<<NH * NTOK * 8 / 256, 256>>>(gpo, gpl, gaoh);

    // 5) output projection (fp16 x1)
    gemm_f16_kernel<<<dim3(DIM / 128, NTOK / 128), 256, GEMM_SMEM>>>(
        gaoh, gwph, b_proj, out, DIM, DIM, 0);
}

// round 13
// speedup vs baseline: 1.6742x; 1.3925x over previous
#include <cuda_runtime.h>
#include <cuda_fp16.h>
#include <cuda_bf16.h>
#include <cstdint>

// Problem constants
#define NTOK   4096      // 64*64 tokens
#define DIM    768
#define NH     12
#define HD     64
#define GRID_HW 64
#define QKSCALE 0.125f   // 64^-0.5
#define LOG2E   1.44269504f
#define M0SHIFT 5.77078016f   // 4.0 * log2(e)
#define NSPLIT 3              // split-KV factor

// ---------------- scratch (device globals; no allocation allowed) ----------
__device__ __align__(16) __half g_qh[NH * NTOK * HD];  // fp16 q PRE-SCALED by 0.125*log2e
__device__ __align__(16) __half g_k[NH * NTOK * HD];   // fp16 k, [head][tok][d]
__device__ __align__(16) __half g_v[NH * HD * NTOK];   // fp16 v TRANSPOSED [head][d][tok]
__device__ float g_relh[NH * NTOK * HD];               // [head][n][kh], LOG2 DOMAIN
__device__ float g_relw[NH * NTOK * HD];               // [head][n][kw], LOG2 DOMAIN
__device__ float g_po[NSPLIT * NH * NTOK * HD];        // split-KV unnormalized O
__device__ float g_pl[NSPLIT * NH * NTOK];             // split-KV partial l
// fp16 GEMM operands
__device__ __align__(16) __half g_xh[NTOK * DIM];      // x fp16
__device__ __align__(16) __half g_wqh[DIM * 3 * DIM];  // w_qkv fp16
__device__ __align__(16) __half g_wph[DIM * DIM];      // w_proj fp16
__device__ __align__(16) __half g_aoh[NTOK * DIM];     // attention out fp16
__device__ __align__(16) __half g_rph[127 * HD];       // rel_pos_h fp16
__device__ __align__(16) __half g_rpw[127 * HD];       // rel_pos_w fp16

// ---------------------------------------------------------------------------
// helpers
// ---------------------------------------------------------------------------
__device__ __forceinline__ __half2 ex2h2(__half2 x) {
    __half2 y;
    asm("ex2.approx.f16x2 %0, %1;"
        : "=r"(*reinterpret_cast<unsigned*>(&y))
        : "r"(*reinterpret_cast<unsigned*>(&x)));
    return y;
}

__device__ __forceinline__ void mma_f16(float c[4],
                                        unsigned a0, unsigned a1, unsigned a2, unsigned a3,
                                        unsigned b0, unsigned b1) {
    asm volatile(
        "mma.sync.aligned.m16n8k16.row.col.f32.f16.f16.f32 "
        "{%0,%1,%2,%3}, {%4,%5,%6,%7}, {%8,%9}, {%0,%1,%2,%3};\n"
        : "+f"(c[0]), "+f"(c[1]), "+f"(c[2]), "+f"(c[3])
        : "r"(a0), "r"(a1), "r"(a2), "r"(a3), "r"(b0), "r"(b1));
}

__device__ __forceinline__ void ldsm4(unsigned* d, uint32_t addr) {
    asm volatile("ldmatrix.sync.aligned.m8n8.x4.shared.b16 {%0,%1,%2,%3}, [%4];\n"
                 : "=r"(d[0]), "=r"(d[1]), "=r"(d[2]), "=r"(d[3]) : "r"(addr));
}

__device__ __forceinline__ void ldsm4t(unsigned* d, uint32_t addr) {
    asm volatile("ldmatrix.sync.aligned.m8n8.x4.trans.shared.b16 {%0,%1,%2,%3}, [%4];\n"
                 : "=r"(d[0]), "=r"(d[1]), "=r"(d[2]), "=r"(d[3]) : "r"(addr));
}

__device__ __forceinline__ void cp16(uint32_t dst, const void* src) {
    asm volatile("cp.async.cg.shared.global [%0], [%1], 16;\n" :: "r"(dst), "l"(src));
}
#define CP_COMMIT() asm volatile("cp.async.commit_group;\n")

// ---------------------------------------------------------------------------
// fused conversion kernel (fp32 -> fp16) for x, w_qkv, w_proj, rel_h, rel_w
// ---------------------------------------------------------------------------
#define NX4  (NTOK * DIM / 4)
#define NWQ4 (DIM * 3 * DIM / 4)
#define NWP4 (DIM * DIM / 4)
#define NRP4 (127 * HD / 4)

__global__ void conv_all_kernel(const float* __restrict__ x,
                                const float* __restrict__ wq,
                                const float* __restrict__ wp,
                                const float* __restrict__ rh,
                                const float* __restrict__ rw)
{
    int i = blockIdx.x * 256 + threadIdx.x;
    const float* src;
    __half* dst;
    int off;
    if (i < NX4)                          { src = x;  dst = g_xh;  off = i; }
    else if ((i -= NX4) < NWQ4)           { src = wq; dst = g_wqh; off = i; }
    else if ((i -= NWQ4) < NWP4)          { src = wp; dst = g_wph; off = i; }
    else if ((i -= NWP4) < NRP4)          { src = rh; dst = g_rph; off = i; }
    else if ((i -= NRP4) < NRP4)          { src = rw; dst = g_rpw; off = i; }
    else return;
    float4 v = ((const float4*)src)[off];
    __half2 h0 = __floats2half2_rn(v.x, v.y);
    __half2 h1 = __floats2half2_rn(v.z, v.w);
    ((uint2*)dst)[off] = make_uint2(*(unsigned*)&h0, *(unsigned*)&h1);
}

// ---------------------------------------------------------------------------
// fp16 x1 GEMM (as round 12; q epilogue now writes pre-scaled fp16)
// ---------------------------------------------------------------------------
#define ASTP 12
#define BST  68
#define A_STAGE_P (128 * ASTP)
#define B_STAGE_P (16 * BST)

__global__ void __launch_bounds__(256)
gemm_f16_kernel(const __half* __restrict__ Ah_g,
                const __half* __restrict__ Bh_g,
                const float* __restrict__ bias,
                float* __restrict__ C,
                int N, int K, int qkv_mode)
{
    extern __shared__ float gsm[];
    float* As  = gsm;
    float* Bhs = As + 2 * A_STAGE_P;

    const int bx = blockIdx.x, by = blockIdx.y;
    const int t  = threadIdx.x;
    const int lane = t & 31, w = t >> 5;
    const int r = lane >> 2, c = lane & 3;
    const int wm = w >> 1, wn = w & 1;
    const int m0 = by * 128, n0 = bx * 128;
    const int mw = wm * 32,  nw = wn * 64;

    const int aRow  = (lane & 7) + ((lane >> 3) & 1) * 8;
    const int aColB = (lane >> 4) * 16;
    const int bRow  = (lane & 7) + ((lane >> 3) & 1) * 8;
    const int bColB = ((lane >> 4) & 1) * 16;

    const int am  = t >> 1;
    const int akh = (t & 1);
    const int bk  = t >> 4;
    const int bn4 = t & 15;

    const __half* Ag = Ah_g + (m0 + am) * K + akh * 8;
    const __half* Bg = Bh_g + n0 + bn4 * 4;

    const uint32_t as_b  = (uint32_t)__cvta_generic_to_shared(As);
    const uint32_t bhs_b = (uint32_t)__cvta_generic_to_shared(Bhs);

    uint4 a4;
    uint2 b4[2];
    float acc[2][8][4];
#pragma unroll
    for (int mg = 0; mg < 2; mg++)
#pragma unroll
        for (int ng = 0; ng < 8; ng++)
#pragma unroll
            for (int j = 0; j < 4; j++) acc[mg][ng][j] = 0.f;

    const int nk = K / 16;

    #define F16_LDG(i) do {                                              \
        const int kg_ = (i) * 16;                                        \
        a4 = *(const uint4*)(Ag + kg_);                                  \
        const __half* bp_ = Bg + (int64_t)(kg_ + bk) * N;                \
        b4[0] = *(const uint2*)(bp_);                                    \
        b4[1] = *(const uint2*)(bp_ + 64);                               \
    } while (0)

    #define F16_STS(s) do {                                              \
        float* as = As + (s) * A_STAGE_P;                                \
        float* bh = Bhs + (s) * B_STAGE_P;                               \
        *(uint4*)&as[am * ASTP + akh * 4] = a4;                          \
        const int wo = bk * BST + bn4 * 2;                               \
        *(uint2*)&bh[wo]      = b4[0];                                   \
        *(uint2*)&bh[wo + 32] = b4[1];                                   \
    } while (0)

    F16_LDG(0);
    F16_STS(0);
    F16_LDG(1);
    __syncthreads();

    for (int i = 0; i < nk; i++) {
        const int s = i & 1;
        const uint32_t aB  = as_b  + (uint32_t)(s * A_STAGE_P * 4) + (mw + aRow) * 48 + aColB;
        const uint32_t bhB = bhs_b + (uint32_t)(s * B_STAGE_P * 4) + bRow * 272 + bColB;

        unsigned ah[2][4];
#pragma unroll
        for (int mg = 0; mg < 2; mg++)
            ldsm4(ah[mg], aB + (uint32_t)(mg * 16 * 48));
#pragma unroll
        for (int g = 0; g < 4; g++) {
            unsigned bh[4];
            ldsm4t(bh, bhB + (uint32_t)((nw + g * 16) * 2));
#pragma unroll
            for (int half = 0; half < 2; half++) {
                const unsigned b0 = bh[half * 2], b1 = bh[half * 2 + 1];
                const int ng = g * 2 + half;
#pragma unroll
                for (int mg = 0; mg < 2; mg++)
                    mma_f16(acc[mg][ng], ah[mg][0], ah[mg][1], ah[mg][2], ah[mg][3], b0, b1);
            }
        }

        if (i + 1 < nk) {
            F16_STS((i + 1) & 1);
            if (i + 2 < nk) F16_LDG(i + 2);
        }
        __syncthreads();
    }

    // ---- epilogue ----
    const float qsc = QKSCALE * LOG2E;
#pragma unroll
    for (int mg = 0; mg < 2; mg++) {
        const int row0 = m0 + mw + mg * 16 + r;
        const int row1 = row0 + 8;
#pragma unroll
        for (int ng = 0; ng < 8; ng++) {
            const int col = n0 + nw + ng * 8 + 2 * c;
            const float bs0 = bias[col], bs1 = bias[col + 1];
            float v00 = acc[mg][ng][0] + bs0, v01 = acc[mg][ng][1] + bs1;
            float v10 = acc[mg][ng][2] + bs0, v11 = acc[mg][ng][3] + bs1;
            if (qkv_mode == 0) {
                *(float2*)&C[(int64_t)row0 * N + col] = make_float2(v00, v01);
                *(float2*)&C[(int64_t)row1 * N + col] = make_float2(v10, v11);
            } else {
                const int part = col / DIM;
                const int rest = col - part * DIM;
                const int head = rest >> 6;
                const int d0   = rest & 63;
                if (part == 0) {
                    // q pre-scaled to log2 domain, fp16
                    *(__half2*)&g_qh[(head * NTOK + row0) * HD + d0] =
                        __floats2half2_rn(v00 * qsc, v01 * qsc);
                    *(__half2*)&g_qh[(head * NTOK + row1) * HD + d0] =
                        __floats2half2_rn(v10 * qsc, v11 * qsc);
                } else if (part == 1) {
                    *(__half2*)&g_k[(head * NTOK + row0) * HD + d0] = __floats2half2_rn(v00, v01);
                    *(__half2*)&g_k[(head * NTOK + row1) * HD + d0] = __floats2half2_rn(v10, v11);
                } else {
                    __half* vt = g_v + head * HD * NTOK;
                    vt[(d0    ) * NTOK + row0] = __float2half_rn(v00);
                    vt[(d0 + 1) * NTOK + row0] = __float2half_rn(v01);
                    vt[(d0    ) * NTOK + row1] = __float2half_rn(v10);
                    vt[(d0 + 1) * NTOK + row1] = __float2half_rn(v11);
                }
            }
        }
    }
}

// ---------------------------------------------------------------------------
// Tensor-core rel-pos: block (fixed 0..63, head, mode), 128 threads = 4 warps.
// A = 64 q rows (fp16, pre-scaled by 0.125*log2e), B = 64 rel_pos rows (fp16).
// out (fp32, log2 domain) = 8 * (A B^T):   8 * 0.125 * log2e = log2e.  EXACT.
// mode 0: token = fixed*64 + row, rp row = fixed - kh + 63   (rel_h)
// mode 1: token = row*64 + fixed, rp row = fixed - kw + 63   (rel_w)
// ---------------------------------------------------------------------------
__global__ void __launch_bounds__(128)
relpos_tc_kernel(const __half* __restrict__ gqh,
                 const __half* __restrict__ rph,
                 const __half* __restrict__ rpw,
                 float* __restrict__ outh,
                 float* __restrict__ outw)
{
    __shared__ __align__(16) char Asm[64 * 144];
    __shared__ __align__(16) char Bsm[64 * 144];

    const int fixed = blockIdx.x;
    const int head  = blockIdx.y;
    const int mode  = blockIdx.z;
    const int t     = threadIdx.x;   // 128
    const int lane  = t & 31;
    const int w     = t >> 5;
    const int r     = lane >> 2;
    const int c     = lane & 3;

    const __half* rp = mode ? rpw : rph;
    float* out = mode ? outw : outh;
    const __half* qbase = gqh + head * NTOK * HD;

    const uint32_t as_sm = (uint32_t)__cvta_generic_to_shared(Asm);
    const uint32_t bs_sm = (uint32_t)__cvta_generic_to_shared(Bsm);

    // load A (64 q rows) and B (64 rp rows): 512 16B chunks each, 4/thread
#pragma unroll
    for (int i = 0; i < 4; i++) {
        const int ch = t + i * 128;
        const int row = ch >> 3, co = (ch & 7) * 16;
        const int tok = mode ? (row * 64 + fixed) : (fixed * 64 + row);
        cp16(as_sm + (uint32_t)(row * 144 + co), (const char*)(qbase + tok * HD) + co);
        cp16(bs_sm + (uint32_t)(row * 144 + co), (const char*)(rp + (fixed - row + 63) * HD) + co);
    }
    CP_COMMIT();
    asm volatile("cp.async.wait_group 0;\n");
    __syncthreads();

    // warp w: A rows w*16..w*16+15
    const uint32_t aB = as_sm + (uint32_t)((w * 16 + (lane & 15)) * 144 + (lane >> 4) * 16);
    const uint32_t bB = bs_sm + (uint32_t)((lane & 15) * 144 + (lane >> 4) * 16);

    unsigned qa[4][4];
#pragma unroll
    for (int kk = 0; kk < 4; kk++)
        ldsm4(qa[kk], aB + (uint32_t)(kk * 32));

    float S[8][4];
#pragma unroll
    for (int n = 0; n < 8; n++)
#pragma unroll
        for (int j = 0; j < 4; j++) S[n][j] = 0.f;

#pragma unroll
    for (int kk = 0; kk < 4; kk++) {
#pragma unroll
        for (int g = 0; g < 4; g++) {
            unsigned bb[4];
            ldsm4(bb, bB + (uint32_t)(g * 16 * 144 + kk * 32));
            mma_f16(S[g*2],   qa[kk][0], qa[kk][1], qa[kk][2], qa[kk][3], bb[0], bb[2]);
            mma_f16(S[g*2+1], qa[kk][0], qa[kk][1], qa[kk][2], qa[kk][3], bb[1], bb[3]);
        }
    }

    // epilogue: scale by 8 -> log2 domain
    const int arow0 = w * 16 + r, arow1 = arow0 + 8;
    const int tok0 = mode ? (arow0 * 64 + fixed) : (fixed * 64 + arow0);
    const int tok1 = mode ? (arow1 * 64 + fixed) : (fixed * 64 + arow1);
    float* o0 = out + (head * NTOK + tok0) * HD;
    float* o1 = out + (head * NTOK + tok1) * HD;
#pragma unroll
    for (int n = 0; n < 8; n++) {
        const int col = n * 8 + 2 * c;
        *(float2*)&o0[col] = make_float2(S[n][0] * 8.f, S[n][1] * 8.f);
        *(float2*)&o1[col] = make_float2(S[n][2] * 8.f, S[n][3] * 8.f);
    }
}

// ---------------------------------------------------------------------------
// Flash attention v13: Q staged via cp.async from pre-scaled g_qh; rel biases
// pre-log2; f16x2 softmax; l via ones-MMA; 3-stage cp.async; split-KV x3.
// ---------------------------------------------------------------------------
#define STRH      72
#define ROW_B     144
#define KV_TILE_B (64 * ROW_B)               // 9216 B per tile
#define PQ_B      (128 * ROW_B)              // 18432 B
#define FLASH_SMEM_B (6 * KV_TILE_B + PQ_B)  // 73728 B
#define ONESH2 0x3C003C00u                    // half2(1,1)

__global__ void __launch_bounds__(128, 2)
flash_v13_kernel(const __half* __restrict__ gqh,
                 const __half* __restrict__ gk,
                 const __half* __restrict__ gvt,
                 const float* __restrict__ grh,
                 const float* __restrict__ grw,
                 float* __restrict__ po,
                 float* __restrict__ pl)
{
    extern __shared__ char smc[];
    char*   Ksc = smc;                        // 3 stages x 64 x 144B
    char*   Vsc = smc + 3 * KV_TILE_B;        // 3 stages x 64 x 144B
    __half* PQh = (__half*)(smc + 6 * KV_TILE_B);   // 128 x 72 halves (Q -> P)

    const int qt   = blockIdx.x;
    const int head = blockIdx.y;
    const int z    = blockIdx.z;      // KV third
    const int ktb  = (z == 0) ? 0 : (22 + 21 * (z - 1));   // 0, 22, 43
    const int nit  = (z == 0) ? 22 : 21;
    const int t    = threadIdx.x;
    const int lane = t & 31;
    const int w    = t >> 5;
    const int r    = lane >> 2;
    const int c    = lane & 3;
    const int mbase = w * 32;

    const __half* qbh  = gqh + (head * NTOK + qt * 128) * HD;
    const __half* kb0  = gk  + head * NTOK * HD;
    const char*   vtb0 = (const char*)(gvt + head * HD * NTOK);
    const float*  rhb  = grh + (head * NTOK + qt * 128 + mbase) * HD;
    const float*  rwb  = grw + (head * NTOK + qt * 128 + mbase) * HD;

    const uint32_t ks_sm = (uint32_t)__cvta_generic_to_shared(Ksc);
    const uint32_t vs_sm = (uint32_t)__cvta_generic_to_shared(Vsc);
    const uint32_t pq_sm = (uint32_t)__cvta_generic_to_shared(PQh);

    #define LOAD_KV(st, kt) do {                                              \
        const char* kb_ = (const char*)(kb0 + (kt) * 64 * HD);                \
        const uint32_t kd_ = ks_sm + (uint32_t)((st) * KV_TILE_B);            \
        const uint32_t vd_ = vs_sm + (uint32_t)((st) * KV_TILE_B);            \
        _Pragma("unroll")                                                     \
        for (int i_ = 0; i_ < 4; i_++) {                                      \
            const int ch_ = t + i_ * 128;                                     \
            const int row_ = ch_ >> 3, co_ = (ch_ & 7) * 16;                  \
            cp16(kd_ + row_ * ROW_B + co_, kb_ + row_ * 128 + co_);           \
            cp16(vd_ + row_ * ROW_B + co_,                                    \
                 vtb0 + row_ * (NTOK * 2) + (kt) * 128 + co_);                \
        }                                                                     \
    } while (0)

    // prologue: prefetch K/V tiles ktb, ktb+1 and Q (all cp.async)
    LOAD_KV(0, ktb);     CP_COMMIT();
    LOAD_KV(1, ktb + 1); CP_COMMIT();
#pragma unroll
    for (int i_ = 0; i_ < 8; i_++) {
        const int ch_ = t + i_ * 128;
        const int row_ = ch_ >> 3, co_ = (ch_ & 7) * 16;
        cp16(pq_sm + (uint32_t)(row_ * ROW_B + co_), (const char*)qbh + row_ * 128 + co_);
    }
    CP_COMMIT();
    asm volatile("cp.async.wait_group 0;\n");
    __syncthreads();

    // Q fragments (persist)
    const uint32_t aBase = pq_sm + (uint32_t)((mbase + (lane & 15)) * ROW_B
                                              + (lane >> 4) * 16);
    unsigned qa[2][4][4];
#pragma unroll
    for (int mb = 0; mb < 2; mb++)
#pragma unroll
        for (int kk = 0; kk < 4; kk++)
            ldsm4(qa[mb][kk], aBase + (uint32_t)(mb * 16 * ROW_B + kk * 32));
    __syncwarp();

    // rw bias (already log2 domain), packed fp16x2: [mb][rowgroup][n]
    __half2 rwh[2][2][8];
#pragma unroll
    for (int mb = 0; mb < 2; mb++)
#pragma unroll
        for (int rg = 0; rg < 2; rg++)
#pragma unroll
            for (int n = 0; n < 8; n++) {
                float2 v = *(const float2*)&rwb[(mb * 16 + rg * 8 + r) * HD + n * 8 + 2 * c];
                rwh[mb][rg][n] = __floats2half2_rn(v.x, v.y);
            }

    float O[2][8][4];
#pragma unroll
    for (int mb = 0; mb < 2; mb++)
#pragma unroll
        for (int n = 0; n < 8; n++)
#pragma unroll
            for (int j = 0; j < 4; j++) O[mb][n][j] = 0.f;
    float lacc[2][4];
#pragma unroll
    for (int mb = 0; mb < 2; mb++)
#pragma unroll
        for (int j = 0; j < 4; j++) lacc[mb][j] = 0.f;

    for (int it = 0; it < nit; it++) {
        const int kt = ktb + it;
        const int s  = it % 3;

        asm volatile("cp.async.wait_group 1;\n");
        __syncthreads();   // tile kt ready; all warps done with stage (it+2)%3

        if (it + 2 < nit) LOAD_KV((it + 2) % 3, kt + 2);
        CP_COMMIT();

        // rh bias (log2 domain) with -M0 shift
        float rh[2][2];
#pragma unroll
        for (int mb = 0; mb < 2; mb++) {
            rh[mb][0] = __ldg(&rhb[(mb * 16 + r) * HD + kt])     - M0SHIFT;
            rh[mb][1] = __ldg(&rhb[(mb * 16 + 8 + r) * HD + kt]) - M0SHIFT;
        }

        const uint32_t kS = ks_sm + (uint32_t)(s * KV_TILE_B)
                              + (lane & 15) * ROW_B + (lane >> 4) * 16;
        const uint32_t vS = vs_sm + (uint32_t)(s * KV_TILE_B)
                              + (lane & 15) * ROW_B + (lane >> 4) * 16;

        // ---- S = Q K^T over full 64 keys ----
        float S[2][8][4];
#pragma unroll
        for (int mb = 0; mb < 2; mb++)
#pragma unroll
            for (int n = 0; n < 8; n++)
#pragma unroll
                for (int j = 0; j < 4; j++) S[mb][n][j] = 0.f;

#pragma unroll
        for (int kk = 0; kk < 4; kk++) {
#pragma unroll
            for (int g = 0; g < 4; g++) {
                unsigned bb[4];
                ldsm4(bb, kS + (uint32_t)(g * 16 * ROW_B + kk * 32));
                mma_f16(S[0][g*2],   qa[0][kk][0], qa[0][kk][1], qa[0][kk][2], qa[0][kk][3], bb[0], bb[2]);
                mma_f16(S[0][g*2+1], qa[0][kk][0], qa[0][kk][1], qa[0][kk][2], qa[0][kk][3], bb[1], bb[3]);
                mma_f16(S[1][g*2],   qa[1][kk][0], qa[1][kk][1], qa[1][kk][2], qa[1][kk][3], bb[0], bb[2]);
                mma_f16(S[1][g*2+1], qa[1][kk][0], qa[1][kk][1], qa[1][kk][2], qa[1][kk][3], bb[1], bb[3]);
            }
        }

        // ---- fixed-shift softmax: p = 2^(S + rh' + rw'), f16x2 exp ----
#pragma unroll
        for (int mb = 0; mb < 2; mb++) {
            const float a0 = rh[mb][0];
            const float a1 = rh[mb][1];
            __half* prow0 = PQh + (mbase + mb * 16 + r) * STRH + 2 * c;
            __half* prow1 = prow0 + 8 * STRH;
#pragma unroll
            for (int n = 0; n < 8; n++) {
                __half2 h01 = __floats2half2_rn(S[mb][n][0] + a0, S[mb][n][1] + a0);
                __half2 h23 = __floats2half2_rn(S[mb][n][2] + a1, S[mb][n][3] + a1);
                __half2 p01 = ex2h2(__hadd2(h01, rwh[mb][0][n]));
                __half2 p23 = ex2h2(__hadd2(h23, rwh[mb][1][n]));
                *(__half2*)(prow0 + n * 8) = p01;
                *(__half2*)(prow1 + n * 8) = p23;
            }
        }
        __syncwarp();   // P rows warp-private

        // ---- O += P V; l += P * ones ----
#pragma unroll
        for (int kk2 = 0; kk2 < 4; kk2++) {
            unsigned pa[2][4];
            ldsm4(pa[0], aBase + (uint32_t)(kk2 * 32));
            ldsm4(pa[1], aBase + (uint32_t)(16 * ROW_B + kk2 * 32));
            mma_f16(lacc[0], pa[0][0], pa[0][1], pa[0][2], pa[0][3], ONESH2, ONESH2);
            mma_f16(lacc[1], pa[1][0], pa[1][1], pa[1][2], pa[1][3], ONESH2, ONESH2);
#pragma unroll
            for (int p = 0; p < 4; p++) {
                unsigned vv[4];
                ldsm4(vv, vS + (uint32_t)(p * 16 * ROW_B + kk2 * 32));
                mma_f16(O[0][p*2],   pa[0][0], pa[0][1], pa[0][2], pa[0][3], vv[0], vv[2]);
                mma_f16(O[0][p*2+1], pa[0][0], pa[0][1], pa[0][2], pa[0][3], vv[1], vv[3]);
                mma_f16(O[1][p*2],   pa[1][0], pa[1][1], pa[1][2], pa[1][3], vv[0], vv[2]);
                mma_f16(O[1][p*2+1], pa[1][0], pa[1][1], pa[1][2], pa[1][3], vv[1], vv[3]);
            }
        }
        __syncwarp();   // P reads done before next iter's stores
    }

    // ---- epilogue ----
    const int pz = z * NH * NTOK + head * NTOK;
#pragma unroll
    for (int mb = 0; mb < 2; mb++) {
        const int row0 = qt * 128 + mbase + mb * 16 + r;
        const int row1 = row0 + 8;
        if (c == 0) {
            pl[pz + row0] = lacc[mb][0];
            pl[pz + row1] = lacc[mb][2];
        }
#pragma unroll
        for (int n = 0; n < 8; n++) {
            const int col = n * 8 + 2 * c;
            *(float2*)&po[(pz + row0) * HD + col] = make_float2(O[mb][n][0], O[mb][n][1]);
            *(float2*)&po[(pz + row1) * HD + col] = make_float2(O[mb][n][2], O[mb][n][3]);
        }
    }
}

// ---------------------------------------------------------------------------
// merge the three KV-third partials -> g_aoh (fp16, feeds proj GEMM)
// ---------------------------------------------------------------------------
__global__ void merge_kernel(const float* __restrict__ po,
                             const float* __restrict__ pl,
                             __half* __restrict__ aoh)
{
    const int gid = blockIdx.x * 256 + threadIdx.x;
    const int dp  = (gid & 7) * 8;
    const int hr  = gid >> 3;
    const int head = hr >> 12, row = hr & 4095;
    const int S = NH * NTOK;

    const float inv = 1.0f / (pl[hr] + pl[S + hr] + pl[2 * S + hr]);

    const float* o0 = po + (size_t)hr * HD + dp;
    const float* o1 = po + (size_t)(S + hr) * HD + dp;
    const float* o2 = po + (size_t)(2 * S + hr) * HD + dp;
    __half* dst = aoh + row * DIM + head * HD + dp;

    uint4 outw;
    unsigned* ow = (unsigned*)&outw;
#pragma unroll
    for (int j = 0; j < 8; j += 2) {
        float x = (o0[j]     + o1[j]     + o2[j])     * inv;
        float y = (o0[j + 1] + o1[j + 1] + o2[j + 1]) * inv;
        __half2 h = __floats2half2_rn(x, y);
        ow[j >> 1] = *(unsigned*)&h;
    }
    *(uint4*)dst = outw;
}

// ---------------------------------------------------------------------------
extern "C" void kernel_launch(void* const* d_in, const int* in_sizes, int n_in,
                              void* d_out, int out_size)
{
    const float* x        = (const float*)d_in[0];
    const float* w_qkv    = (const float*)d_in[1];
    const float* b_qkv    = (const float*)d_in[2];
    const float* w_proj   = (const float*)d_in[3];
    const float* b_proj   = (const float*)d_in[4];
    const float* rel_h    = (const float*)d_in[5];
    const float* rel_w    = (const float*)d_in[6];
    float* out = (float*)d_out;

    float *grh, *grw, *gpo, *gpl;
    __half *gqh, *gk, *gv, *gxh, *gwqh, *gwph, *gaoh, *grph, *grpw;
    cudaGetSymbolAddress((void**)&gqh,  g_qh);
    cudaGetSymbolAddress((void**)&gk,   g_k);
    cudaGetSymbolAddress((void**)&gv,   g_v);
    cudaGetSymbolAddress((void**)&grh,  g_relh);
    cudaGetSymbolAddress((void**)&grw,  g_relw);
    cudaGetSymbolAddress((void**)&gpo,  g_po);
    cudaGetSymbolAddress((void**)&gpl,  g_pl);
    cudaGetSymbolAddress((void**)&gxh,  g_xh);
    cudaGetSymbolAddress((void**)&gwqh, g_wqh);
    cudaGetSymbolAddress((void**)&gwph, g_wph);
    cudaGetSymbolAddress((void**)&gaoh, g_aoh);
    cudaGetSymbolAddress((void**)&grph, g_rph);
    cudaGetSymbolAddress((void**)&grpw, g_rpw);

    // 0) fused conversion of all operands to fp16
    const int NCONV = NX4 + NWQ4 + NWP4 + 2 * NRP4;
    conv_all_kernel<<<(NCONV + 255) / 256, 256>>>(x, w_qkv, w_proj, rel_h, rel_w);

    static const int GEMM_SMEM = (2 * A_STAGE_P + 2 * B_STAGE_P) * (int)sizeof(float);  // 20,992 B
    cudaFuncSetAttribute(gemm_f16_kernel,
                         cudaFuncAttributeMaxDynamicSharedMemorySize, GEMM_SMEM);

    // 1) QKV GEMM (fp16 x1): q pre-scaled fp16, k fp16, v^T fp16
    gemm_f16_kernel<<<dim3(3 * DIM / 128, NTOK / 128), 256, GEMM_SMEM>>>(
        gxh, gwqh, b_qkv, nullptr, 3 * DIM, DIM, 1);

    // 2) rel_h / rel_w via tensor cores (log2-domain output)
    relpos_tc_kernel<<<dim3(GRID_HW, NH, 2), 128>>>(gqh, grph, grpw, grh, grw);

    // 3) flash attention v13 (split-KV x3)
    cudaFuncSetAttribute(flash_v13_kernel,
                         cudaFuncAttributeMaxDynamicSharedMemorySize, FLASH_SMEM_B);
    flash_v13_kernel<<<dim3(NTOK / 128, NH, NSPLIT), 128, FLASH_SMEM_B>>>(
        gqh, gk, gv, grh, grw, gpo, gpl);

    // 4) merge partials -> fp16 ao
    merge_kernel<<<NH * NTOK * 8 / 256, 256>>>(gpo, gpl, gaoh);

    // 5) output projection (fp16 x1)
    gemm_f16_kernel<<<dim3(DIM / 128, NTOK / 128), 256, GEMM_SMEM>>>(
        gaoh, gwph, b_proj, out, DIM, DIM, 0);
}

// round 14
// speedup vs baseline: 1.7057x; 1.0188x over previous
#include <cuda_runtime.h>
#include <cuda_fp16.h>
#include <cuda_bf16.h>
#include <cstdint>

// Problem constants
#define NTOK   4096      // 64*64 tokens
#define DIM    768
#define NH     12
#define HD     64
#define GRID_HW 64
#define QKSCALE 0.125f   // 64^-0.5
#define LOG2E   1.44269504f
#define M0SHIFT 5.77078016f   // 4.0 * log2(e)
#define NSPLIT 3              // split-KV factor

// ---------------- scratch (device globals; no allocation allowed) ----------
__device__ __align__(16) __half g_qh[NH * NTOK * HD];  // fp16 q PRE-SCALED by 0.125*log2e
__device__ __align__(16) __half g_k[NH * NTOK * HD];   // fp16 k, [head][tok][d]
__device__ __align__(16) __half g_v[NH * HD * NTOK];   // fp16 v TRANSPOSED [head][d][tok]
__device__ float g_relh[NH * NTOK * HD];               // [head][n][kh], LOG2 DOMAIN
__device__ float g_relw[NH * NTOK * HD];               // [head][n][kw], LOG2 DOMAIN
__device__ float g_po[NSPLIT * NH * NTOK * HD];        // split-KV unnormalized O
__device__ float g_pl[NSPLIT * NH * NTOK];             // split-KV partial l
// fp16 GEMM operands
__device__ __align__(16) __half g_xh[NTOK * DIM];      // x fp16
__device__ __align__(16) __half g_wqh[DIM * 3 * DIM];  // w_qkv fp16
__device__ __align__(16) __half g_wph[DIM * DIM];      // w_proj fp16
__device__ __align__(16) __half g_aoh[NTOK * DIM];     // attention out fp16
__device__ __align__(16) __half g_rph[127 * HD];       // rel_pos_h fp16
__device__ __align__(16) __half g_rpw[127 * HD];       // rel_pos_w fp16

// ---------------------------------------------------------------------------
// helpers
// ---------------------------------------------------------------------------
__device__ __forceinline__ __half2 ex2h2(__half2 x) {
    __half2 y;
    asm("ex2.approx.f16x2 %0, %1;"
        : "=r"(*reinterpret_cast<unsigned*>(&y))
        : "r"(*reinterpret_cast<unsigned*>(&x)));
    return y;
}

__device__ __forceinline__ void mma_f16(float c[4],
                                        unsigned a0, unsigned a1, unsigned a2, unsigned a3,
                                        unsigned b0, unsigned b1) {
    asm volatile(
        "mma.sync.aligned.m16n8k16.row.col.f32.f16.f16.f32 "
        "{%0,%1,%2,%3}, {%4,%5,%6,%7}, {%8,%9}, {%0,%1,%2,%3};\n"
        : "+f"(c[0]), "+f"(c[1]), "+f"(c[2]), "+f"(c[3])
        : "r"(a0), "r"(a1), "r"(a2), "r"(a3), "r"(b0), "r"(b1));
}

__device__ __forceinline__ void ldsm4(unsigned* d, uint32_t addr) {
    asm volatile("ldmatrix.sync.aligned.m8n8.x4.shared.b16 {%0,%1,%2,%3}, [%4];\n"
                 : "=r"(d[0]), "=r"(d[1]), "=r"(d[2]), "=r"(d[3]) : "r"(addr));
}

__device__ __forceinline__ void ldsm4t(unsigned* d, uint32_t addr) {
    asm volatile("ldmatrix.sync.aligned.m8n8.x4.trans.shared.b16 {%0,%1,%2,%3}, [%4];\n"
                 : "=r"(d[0]), "=r"(d[1]), "=r"(d[2]), "=r"(d[3]) : "r"(addr));
}

__device__ __forceinline__ void cp16(uint32_t dst, const void* src) {
    asm volatile("cp.async.cg.shared.global [%0], [%1], 16;\n" :: "r"(dst), "l"(src));
}
#define CP_COMMIT() asm volatile("cp.async.commit_group;\n")

// ---------------------------------------------------------------------------
// fused conversion kernel (fp32 -> fp16) for x, w_qkv, w_proj, rel_h, rel_w
// ---------------------------------------------------------------------------
#define NX4  (NTOK * DIM / 4)
#define NWQ4 (DIM * 3 * DIM / 4)
#define NWP4 (DIM * DIM / 4)
#define NRP4 (127 * HD / 4)

__global__ void conv_all_kernel(const float* __restrict__ x,
                                const float* __restrict__ wq,
                                const float* __restrict__ wp,
                                const float* __restrict__ rh,
                                const float* __restrict__ rw)
{
    int i = blockIdx.x * 256 + threadIdx.x;
    const float* src;
    __half* dst;
    int off;
    if (i < NX4)                          { src = x;  dst = g_xh;  off = i; }
    else if ((i -= NX4) < NWQ4)           { src = wq; dst = g_wqh; off = i; }
    else if ((i -= NWQ4) < NWP4)          { src = wp; dst = g_wph; off = i; }
    else if ((i -= NWP4) < NRP4)          { src = rh; dst = g_rph; off = i; }
    else if ((i -= NRP4) < NRP4)          { src = rw; dst = g_rpw; off = i; }
    else return;
    float4 v = ((const float4*)src)[off];
    __half2 h0 = __floats2half2_rn(v.x, v.y);
    __half2 h1 = __floats2half2_rn(v.z, v.w);
    ((uint2*)dst)[off] = make_uint2(*(unsigned*)&h0, *(unsigned*)&h1);
}

// ---------------------------------------------------------------------------
// fp16 x1 GEMM, 3-stage cp.async pipeline, ONE __syncthreads per k16 chunk.
// 128x128 tiles, 256 threads = 8 warps (4m x 2n).
// A stage: 128 rows x 32B (+16B pad) = 6144B.  B stage: 16 rows x 256B (+16B) = 4352B.
// qkv_mode 1: scatter q (pre-scaled fp16) / k / v^T.  mode 0: C = acc + bias.
// ---------------------------------------------------------------------------
#define AST_B 48
#define BST_B 272
#define A_STG_B (128 * AST_B)              // 6144
#define B_STG_B (16 * BST_B)               // 4352
#define GEMM_SMEM_B (3 * (A_STG_B + B_STG_B))  // 31488

__global__ void __launch_bounds__(256)
gemm_f16_kernel(const __half* __restrict__ Ah_g,
                const __half* __restrict__ Bh_g,
                const float* __restrict__ bias,
                float* __restrict__ C,
                int N, int K, int qkv_mode)
{
    extern __shared__ char gsmc[];
    char* Asm = gsmc;                      // 3 x A_STG_B
    char* Bsm = gsmc + 3 * A_STG_B;        // 3 x B_STG_B

    const int bx = blockIdx.x, by = blockIdx.y;
    const int t  = threadIdx.x;
    const int lane = t & 31, w = t >> 5;
    const int r = lane >> 2, c = lane & 3;
    const int wm = w >> 1, wn = w & 1;
    const int m0 = by * 128, n0 = bx * 128;
    const int mw = wm * 32,  nw = wn * 64;

    // ldsm lane patterns
    const int aRow  = lane & 15;
    const int aColB = (lane >> 4) * 16;
    const int bRow  = (lane & 7) + ((lane >> 3) & 1) * 8;
    const int bColB = ((lane >> 4) & 1) * 16;

    // cp.async staging ids: one 16B chunk per thread per operand
    const int arow = t >> 1;              // 0..127
    const int acol = (t & 1) * 16;        // 0 or 16 bytes
    const int brow = t >> 4;              // 0..15
    const int bcol = (t & 15) * 16;       // 0..240 bytes

    const char* Ag = (const char*)(Ah_g + (int64_t)(m0 + arow) * K) + acol;
    const char* Bg = (const char*)(Bh_g + n0) + bcol;

    const uint32_t as_b = (uint32_t)__cvta_generic_to_shared(Asm);
    const uint32_t bs_b = (uint32_t)__cvta_generic_to_shared(Bsm);
    const uint32_t a_dst = as_b + (uint32_t)(arow * AST_B + acol);
    const uint32_t b_dst = bs_b + (uint32_t)(brow * BST_B + bcol);

    float acc[2][8][4];
#pragma unroll
    for (int mg = 0; mg < 2; mg++)
#pragma unroll
        for (int ng = 0; ng < 8; ng++)
#pragma unroll
            for (int j = 0; j < 4; j++) acc[mg][ng][j] = 0.f;

    const int nk = K / 16;

    #define G_LDG(st, i) do {                                               \
        const int kg_ = (i) * 16;                                           \
        cp16(a_dst + (uint32_t)((st) * A_STG_B), Ag + kg_ * 2);             \
        cp16(b_dst + (uint32_t)((st) * B_STG_B),                            \
             Bg + (int64_t)(kg_ + brow) * N * 2);                           \
    } while (0)

    G_LDG(0, 0); CP_COMMIT();
    G_LDG(1, 1); CP_COMMIT();

    for (int i = 0; i < nk; i++) {
        const int s = i % 3;
        asm volatile("cp.async.wait_group 1;\n");
        __syncthreads();                   // tile i ready; stage (i+2)%3 free

        if (i + 2 < nk) G_LDG((i + 2) % 3, i + 2);
        CP_COMMIT();

        const uint32_t aB  = as_b + (uint32_t)(s * A_STG_B + (mw + aRow) * AST_B + aColB);
        const uint32_t bhB = bs_b + (uint32_t)(s * B_STG_B + bRow * BST_B + bColB);

        unsigned ah[2][4];
#pragma unroll
        for (int mg = 0; mg < 2; mg++)
            ldsm4(ah[mg], aB + (uint32_t)(mg * 16 * AST_B));
#pragma unroll
        for (int g = 0; g < 4; g++) {
            unsigned bh[4];
            ldsm4t(bh, bhB + (uint32_t)((nw + g * 16) * 2));
#pragma unroll
            for (int half = 0; half < 2; half++) {
                const unsigned b0 = bh[half * 2], b1 = bh[half * 2 + 1];
                const int ng = g * 2 + half;
#pragma unroll
                for (int mg = 0; mg < 2; mg++)
                    mma_f16(acc[mg][ng], ah[mg][0], ah[mg][1], ah[mg][2], ah[mg][3], b0, b1);
            }
        }
    }

    // ---- epilogue ----
    const float qsc = QKSCALE * LOG2E;
#pragma unroll
    for (int mg = 0; mg < 2; mg++) {
        const int row0 = m0 + mw + mg * 16 + r;
        const int row1 = row0 + 8;
#pragma unroll
        for (int ng = 0; ng < 8; ng++) {
            const int col = n0 + nw + ng * 8 + 2 * c;
            const float bs0 = bias[col], bs1 = bias[col + 1];
            float v00 = acc[mg][ng][0] + bs0, v01 = acc[mg][ng][1] + bs1;
            float v10 = acc[mg][ng][2] + bs0, v11 = acc[mg][ng][3] + bs1;
            if (qkv_mode == 0) {
                *(float2*)&C[(int64_t)row0 * N + col] = make_float2(v00, v01);
                *(float2*)&C[(int64_t)row1 * N + col] = make_float2(v10, v11);
            } else {
                const int part = col / DIM;
                const int rest = col - part * DIM;
                const int head = rest >> 6;
                const int d0   = rest & 63;
                if (part == 0) {
                    *(__half2*)&g_qh[(head * NTOK + row0) * HD + d0] =
                        __floats2half2_rn(v00 * qsc, v01 * qsc);
                    *(__half2*)&g_qh[(head * NTOK + row1) * HD + d0] =
                        __floats2half2_rn(v10 * qsc, v11 * qsc);
                } else if (part == 1) {
                    *(__half2*)&g_k[(head * NTOK + row0) * HD + d0] = __floats2half2_rn(v00, v01);
                    *(__half2*)&g_k[(head * NTOK + row1) * HD + d0] = __floats2half2_rn(v10, v11);
                } else {
                    __half* vt = g_v + head * HD * NTOK;
                    vt[(d0    ) * NTOK + row0] = __float2half_rn(v00);
                    vt[(d0 + 1) * NTOK + row0] = __float2half_rn(v01);
                    vt[(d0    ) * NTOK + row1] = __float2half_rn(v10);
                    vt[(d0 + 1) * NTOK + row1] = __float2half_rn(v11);
                }
            }
        }
    }
}

// ---------------------------------------------------------------------------
// Tensor-core rel-pos (unchanged from round 13)
// ---------------------------------------------------------------------------
__global__ void __launch_bounds__(128)
relpos_tc_kernel(const __half* __restrict__ gqh,
                 const __half* __restrict__ rph,
                 const __half* __restrict__ rpw,
                 float* __restrict__ outh,
                 float* __restrict__ outw)
{
    __shared__ __align__(16) char Asm[64 * 144];
    __shared__ __align__(16) char Bsm[64 * 144];

    const int fixed = blockIdx.x;
    const int head  = blockIdx.y;
    const int mode  = blockIdx.z;
    const int t     = threadIdx.x;
    const int lane  = t & 31;
    const int w     = t >> 5;
    const int r     = lane >> 2;
    const int c     = lane & 3;

    const __half* rp = mode ? rpw : rph;
    float* out = mode ? outw : outh;
    const __half* qbase = gqh + head * NTOK * HD;

    const uint32_t as_sm = (uint32_t)__cvta_generic_to_shared(Asm);
    const uint32_t bs_sm = (uint32_t)__cvta_generic_to_shared(Bsm);

#pragma unroll
    for (int i = 0; i < 4; i++) {
        const int ch = t + i * 128;
        const int row = ch >> 3, co = (ch & 7) * 16;
        const int tok = mode ? (row * 64 + fixed) : (fixed * 64 + row);
        cp16(as_sm + (uint32_t)(row * 144 + co), (const char*)(qbase + tok * HD) + co);
        cp16(bs_sm + (uint32_t)(row * 144 + co), (const char*)(rp + (fixed - row + 63) * HD) + co);
    }
    CP_COMMIT();
    asm volatile("cp.async.wait_group 0;\n");
    __syncthreads();

    const uint32_t aB = as_sm + (uint32_t)((w * 16 + (lane & 15)) * 144 + (lane >> 4) * 16);
    const uint32_t bB = bs_sm + (uint32_t)((lane & 15) * 144 + (lane >> 4) * 16);

    unsigned qa[4][4];
#pragma unroll
    for (int kk = 0; kk < 4; kk++)
        ldsm4(qa[kk], aB + (uint32_t)(kk * 32));

    float S[8][4];
#pragma unroll
    for (int n = 0; n < 8; n++)
#pragma unroll
        for (int j = 0; j < 4; j++) S[n][j] = 0.f;

#pragma unroll
    for (int kk = 0; kk < 4; kk++) {
#pragma unroll
        for (int g = 0; g < 4; g++) {
            unsigned bb[4];
            ldsm4(bb, bB + (uint32_t)(g * 16 * 144 + kk * 32));
            mma_f16(S[g*2],   qa[kk][0], qa[kk][1], qa[kk][2], qa[kk][3], bb[0], bb[2]);
            mma_f16(S[g*2+1], qa[kk][0], qa[kk][1], qa[kk][2], qa[kk][3], bb[1], bb[3]);
        }
    }

    const int arow0 = w * 16 + r, arow1 = arow0 + 8;
    const int tok0 = mode ? (arow0 * 64 + fixed) : (fixed * 64 + arow0);
    const int tok1 = mode ? (arow1 * 64 + fixed) : (fixed * 64 + arow1);
    float* o0 = out + (head * NTOK + tok0) * HD;
    float* o1 = out + (head * NTOK + tok1) * HD;
#pragma unroll
    for (int n = 0; n < 8; n++) {
        const int col = n * 8 + 2 * c;
        *(float2*)&o0[col] = make_float2(S[n][0] * 8.f, S[n][1] * 8.f);
        *(float2*)&o1[col] = make_float2(S[n][2] * 8.f, S[n][3] * 8.f);
    }
}

// ---------------------------------------------------------------------------
// Flash attention v13 (unchanged from round 13 best)
// ---------------------------------------------------------------------------
#define STRH      72
#define ROW_B     144
#define KV_TILE_B (64 * ROW_B)
#define PQ_B      (128 * ROW_B)
#define FLASH_SMEM_B (6 * KV_TILE_B + PQ_B)  // 73728 B
#define ONESH2 0x3C003C00u

__global__ void __launch_bounds__(128, 2)
flash_v13_kernel(const __half* __restrict__ gqh,
                 const __half* __restrict__ gk,
                 const __half* __restrict__ gvt,
                 const float* __restrict__ grh,
                 const float* __restrict__ grw,
                 float* __restrict__ po,
                 float* __restrict__ pl)
{
    extern __shared__ char smc[];
    char*   Ksc = smc;
    char*   Vsc = smc + 3 * KV_TILE_B;
    __half* PQh = (__half*)(smc + 6 * KV_TILE_B);

    const int qt   = blockIdx.x;
    const int head = blockIdx.y;
    const int z    = blockIdx.z;
    const int ktb  = (z == 0) ? 0 : (22 + 21 * (z - 1));
    const int nit  = (z == 0) ? 22 : 21;
    const int t    = threadIdx.x;
    const int lane = t & 31;
    const int w    = t >> 5;
    const int r    = lane >> 2;
    const int c    = lane & 3;
    const int mbase = w * 32;

    const __half* qbh  = gqh + (head * NTOK + qt * 128) * HD;
    const __half* kb0  = gk  + head * NTOK * HD;
    const char*   vtb0 = (const char*)(gvt + head * HD * NTOK);
    const float*  rhb  = grh + (head * NTOK + qt * 128 + mbase) * HD;
    const float*  rwb  = grw + (head * NTOK + qt * 128 + mbase) * HD;

    const uint32_t ks_sm = (uint32_t)__cvta_generic_to_shared(Ksc);
    const uint32_t vs_sm = (uint32_t)__cvta_generic_to_shared(Vsc);
    const uint32_t pq_sm = (uint32_t)__cvta_generic_to_shared(PQh);

    #define LOAD_KV(st, kt) do {                                              \
        const char* kb_ = (const char*)(kb0 + (kt) * 64 * HD);                \
        const uint32_t kd_ = ks_sm + (uint32_t)((st) * KV_TILE_B);            \
        const uint32_t vd_ = vs_sm + (uint32_t)((st) * KV_TILE_B);            \
        _Pragma("unroll")                                                     \
        for (int i_ = 0; i_ < 4; i_++) {                                      \
            const int ch_ = t + i_ * 128;                                     \
            const int row_ = ch_ >> 3, co_ = (ch_ & 7) * 16;                  \
            cp16(kd_ + row_ * ROW_B + co_, kb_ + row_ * 128 + co_);           \
            cp16(vd_ + row_ * ROW_B + co_,                                    \
                 vtb0 + row_ * (NTOK * 2) + (kt) * 128 + co_);                \
        }                                                                     \
    } while (0)

    LOAD_KV(0, ktb);     CP_COMMIT();
    LOAD_KV(1, ktb + 1); CP_COMMIT();
#pragma unroll
    for (int i_ = 0; i_ < 8; i_++) {
        const int ch_ = t + i_ * 128;
        const int row_ = ch_ >> 3, co_ = (ch_ & 7) * 16;
        cp16(pq_sm + (uint32_t)(row_ * ROW_B + co_), (const char*)qbh + row_ * 128 + co_);
    }
    CP_COMMIT();
    asm volatile("cp.async.wait_group 0;\n");
    __syncthreads();

    const uint32_t aBase = pq_sm + (uint32_t)((mbase + (lane & 15)) * ROW_B
                                              + (lane >> 4) * 16);
    unsigned qa[2][4][4];
#pragma unroll
    for (int mb = 0; mb < 2; mb++)
#pragma unroll
        for (int kk = 0; kk < 4; kk++)
            ldsm4(qa[mb][kk], aBase + (uint32_t)(mb * 16 * ROW_B + kk * 32));
    __syncwarp();

    __half2 rwh[2][2][8];
#pragma unroll
    for (int mb = 0; mb < 2; mb++)
#pragma unroll
        for (int rg = 0; rg < 2; rg++)
#pragma unroll
            for (int n = 0; n < 8; n++) {
                float2 v = *(const float2*)&rwb[(mb * 16 + rg * 8 + r) * HD + n * 8 + 2 * c];
                rwh[mb][rg][n] = __floats2half2_rn(v.x, v.y);
            }

    float O[2][8][4];
#pragma unroll
    for (int mb = 0; mb < 2; mb++)
#pragma unroll
        for (int n = 0; n < 8; n++)
#pragma unroll
            for (int j = 0; j < 4; j++) O[mb][n][j] = 0.f;
    float lacc[2][4];
#pragma unroll
    for (int mb = 0; mb < 2; mb++)
#pragma unroll
        for (int j = 0; j < 4; j++) lacc[mb][j] = 0.f;

    for (int it = 0; it < nit; it++) {
        const int kt = ktb + it;
        const int s  = it % 3;

        asm volatile("cp.async.wait_group 1;\n");
        __syncthreads();

        if (it + 2 < nit) LOAD_KV((it + 2) % 3, kt + 2);
        CP_COMMIT();

        float rh[2][2];
#pragma unroll
        for (int mb = 0; mb < 2; mb++) {
            rh[mb][0] = __ldg(&rhb[(mb * 16 + r) * HD + kt])     - M0SHIFT;
            rh[mb][1] = __ldg(&rhb[(mb * 16 + 8 + r) * HD + kt]) - M0SHIFT;
        }

        const uint32_t kS = ks_sm + (uint32_t)(s * KV_TILE_B)
                              + (lane & 15) * ROW_B + (lane >> 4) * 16;
        const uint32_t vS = vs_sm + (uint32_t)(s * KV_TILE_B)
                              + (lane & 15) * ROW_B + (lane >> 4) * 16;

        float S[2][8][4];
#pragma unroll
        for (int mb = 0; mb < 2; mb++)
#pragma unroll
            for (int n = 0; n < 8; n++)
#pragma unroll
                for (int j = 0; j < 4; j++) S[mb][n][j] = 0.f;

#pragma unroll
        for (int kk = 0; kk < 4; kk++) {
#pragma unroll
            for (int g = 0; g < 4; g++) {
                unsigned bb[4];
                ldsm4(bb, kS + (uint32_t)(g * 16 * ROW_B + kk * 32));
                mma_f16(S[0][g*2],   qa[0][kk][0], qa[0][kk][1], qa[0][kk][2], qa[0][kk][3], bb[0], bb[2]);
                mma_f16(S[0][g*2+1], qa[0][kk][0], qa[0][kk][1], qa[0][kk][2], qa[0][kk][3], bb[1], bb[3]);
                mma_f16(S[1][g*2],   qa[1][kk][0], qa[1][kk][1], qa[1][kk][2], qa[1][kk][3], bb[0], bb[2]);
                mma_f16(S[1][g*2+1], qa[1][kk][0], qa[1][kk][1], qa[1][kk][2], qa[1][kk][3], bb[1], bb[3]);
            }
        }

#pragma unroll
        for (int mb = 0; mb < 2; mb++) {
            const float a0 = rh[mb][0];
            const float a1 = rh[mb][1];
            __half* prow0 = PQh + (mbase + mb * 16 + r) * STRH + 2 * c;
            __half* prow1 = prow0 + 8 * STRH;
#pragma unroll
            for (int n = 0; n < 8; n++) {
                __half2 h01 = __floats2half2_rn(S[mb][n][0] + a0, S[mb][n][1] + a0);
                __half2 h23 = __floats2half2_rn(S[mb][n][2] + a1, S[mb][n][3] + a1);
                __half2 p01 = ex2h2(__hadd2(h01, rwh[mb][0][n]));
                __half2 p23 = ex2h2(__hadd2(h23, rwh[mb][1][n]));
                *(__half2*)(prow0 + n * 8) = p01;
                *(__half2*)(prow1 + n * 8) = p23;
            }
        }
        __syncwarp();

#pragma unroll
        for (int kk2 = 0; kk2 < 4; kk2++) {
            unsigned pa[2][4];
            ldsm4(pa[0], aBase + (uint32_t)(kk2 * 32));
            ldsm4(pa[1], aBase + (uint32_t)(16 * ROW_B + kk2 * 32));
            mma_f16(lacc[0], pa[0][0], pa[0][1], pa[0][2], pa[0][3], ONESH2, ONESH2);
            mma_f16(lacc[1], pa[1][0], pa[1][1], pa[1][2], pa[1][3], ONESH2, ONESH2);
#pragma unroll
            for (int p = 0; p < 4; p++) {
                unsigned vv[4];
                ldsm4(vv, vS + (uint32_t)(p * 16 * ROW_B + kk2 * 32));
                mma_f16(O[0][p*2],   pa[0][0], pa[0][1], pa[0][2], pa[0][3], vv[0], vv[2]);
                mma_f16(O[0][p*2+1], pa[0][0], pa[0][1], pa[0][2], pa[0][3], vv[1], vv[3]);
                mma_f16(O[1][p*2],   pa[1][0], pa[1][1], pa[1][2], pa[1][3], vv[0], vv[2]);
                mma_f16(O[1][p*2+1], pa[1][0], pa[1][1], pa[1][2], pa[1][3], vv[1], vv[3]);
            }
        }
        __syncwarp();
    }

    const int pz = z * NH * NTOK + head * NTOK;
#pragma unroll
    for (int mb = 0; mb < 2; mb++) {
        const int row0 = qt * 128 + mbase + mb * 16 + r;
        const int row1 = row0 + 8;
        if (c == 0) {
            pl[pz + row0] = lacc[mb][0];
            pl[pz + row1] = lacc[mb][2];
        }
#pragma unroll
        for (int n = 0; n < 8; n++) {
            const int col = n * 8 + 2 * c;
            *(float2*)&po[(pz + row0) * HD + col] = make_float2(O[mb][n][0], O[mb][n][1]);
            *(float2*)&po[(pz + row1) * HD + col] = make_float2(O[mb][n][2], O[mb][n][3]);
        }
    }
}

// ---------------------------------------------------------------------------
// merge the three KV-third partials -> g_aoh (fp16, feeds proj GEMM)
// ---------------------------------------------------------------------------
__global__ void merge_kernel(const float* __restrict__ po,
                             const float* __restrict__ pl,
                             __half* __restrict__ aoh)
{
    const int gid = blockIdx.x * 256 + threadIdx.x;
    const int dp  = (gid & 7) * 8;
    const int hr  = gid >> 3;
    const int head = hr >> 12, row = hr & 4095;
    const int S = NH * NTOK;

    const float inv = 1.0f / (pl[hr] + pl[S + hr] + pl[2 * S + hr]);

    const float* o0 = po + (size_t)hr * HD + dp;
    const float* o1 = po + (size_t)(S + hr) * HD + dp;
    const float* o2 = po + (size_t)(2 * S + hr) * HD + dp;
    __half* dst = aoh + row * DIM + head * HD + dp;

    uint4 outw;
    unsigned* ow = (unsigned*)&outw;
#pragma unroll
    for (int j = 0; j < 8; j += 2) {
        float x = (o0[j]     + o1[j]     + o2[j])     * inv;
        float y = (o0[j + 1] + o1[j + 1] + o2[j + 1]) * inv;
        __half2 h = __floats2half2_rn(x, y);
        ow[j >> 1] = *(unsigned*)&h;
    }
    *(uint4*)dst = outw;
}

// ---------------------------------------------------------------------------
extern "C" void kernel_launch(void* const* d_in, const int* in_sizes, int n_in,
                              void* d_out, int out_size)
{
    const float* x        = (const float*)d_in[0];
    const float* w_qkv    = (const float*)d_in[1];
    const float* b_qkv    = (const float*)d_in[2];
    const float* w_proj   = (const float*)d_in[3];
    const float* b_proj   = (const float*)d_in[4];
    const float* rel_h    = (const float*)d_in[5];
    const float* rel_w    = (const float*)d_in[6];
    float* out = (float*)d_out;

    float *grh, *grw, *gpo, *gpl;
    __half *gqh, *gk, *gv, *gxh, *gwqh, *gwph, *gaoh, *grph, *grpw;
    cudaGetSymbolAddress((void**)&gqh,  g_qh);
    cudaGetSymbolAddress((void**)&gk,   g_k);
    cudaGetSymbolAddress((void**)&gv,   g_v);
    cudaGetSymbolAddress((void**)&grh,  g_relh);
    cudaGetSymbolAddress((void**)&grw,  g_relw);
    cudaGetSymbolAddress((void**)&gpo,  g_po);
    cudaGetSymbolAddress((void**)&gpl,  g_pl);
    cudaGetSymbolAddress((void**)&gxh,  g_xh);
    cudaGetSymbolAddress((void**)&gwqh, g_wqh);
    cudaGetSymbolAddress((void**)&gwph, g_wph);
    cudaGetSymbolAddress((void**)&gaoh, g_aoh);
    cudaGetSymbolAddress((void**)&grph, g_rph);
    cudaGetSymbolAddress((void**)&grpw, g_rpw);

    // 0) fused conversion of all operands to fp16
    const int NCONV = NX4 + NWQ4 + NWP4 + 2 * NRP4;
    conv_all_kernel<<<(NCONV + 255) / 256, 256>>>(x, w_qkv, w_proj, rel_h, rel_w);

    cudaFuncSetAttribute(gemm_f16_kernel,
                         cudaFuncAttributeMaxDynamicSharedMemorySize, GEMM_SMEM_B);

    // 1) QKV GEMM (fp16 x1, 3-stage cp.async)
    gemm_f16_kernel<<<dim3(3 * DIM / 128, NTOK / 128), 256, GEMM_SMEM_B>>>(
        gxh, gwqh, b_qkv, nullptr, 3 * DIM, DIM, 1);

    // 2) rel_h / rel_w via tensor cores
    relpos_tc_kernel<<<dim3(GRID_HW, NH, 2), 128>>>(gqh, grph, grpw, grh, grw);

    // 3) flash attention v13 (split-KV x3)
    cudaFuncSetAttribute(flash_v13_kernel,
                         cudaFuncAttributeMaxDynamicSharedMemorySize, FLASH_SMEM_B);
    flash_v13_kernel<<<dim3(NTOK / 128, NH, NSPLIT), 128, FLASH_SMEM_B>>>(
        gqh, gk, gv, grh, grw, gpo, gpl);

    // 4) merge partials -> fp16 ao
    merge_kernel<<<NH * NTOK * 8 / 256, 256>>>(gpo, gpl, gaoh);

    // 5) output projection (fp16 x1, 3-stage cp.async)
    gemm_f16_kernel<<<dim3(DIM / 128, NTOK / 128), 256, GEMM_SMEM_B>>>(
        gaoh, gwph, b_proj, out, DIM, DIM, 0);
}

// round 15
// speedup vs baseline: 1.7097x; 1.0023x over previous
#include <cuda_runtime.h>
#include <cuda_fp16.h>
#include <cuda_bf16.h>
#include <cstdint>

// Problem constants
#define NTOK   4096      // 64*64 tokens
#define DIM    768
#define NH     12
#define HD     64
#define GRID_HW 64
#define QKSCALE 0.125f   // 64^-0.5
#define LOG2E   1.44269504f
#define M0SHIFT 5.77078016f   // 4.0 * log2(e)
#define NSPLIT 3              // split-KV factor

// ---------------- scratch (device globals; no allocation allowed) ----------
__device__ __align__(16) __half g_qh[NH * NTOK * HD];  // fp16 q PRE-SCALED by 0.125*log2e
__device__ __align__(16) __half g_k[NH * NTOK * HD];   // fp16 k, [head][tok][d]
__device__ __align__(16) __half g_v[NH * HD * NTOK];   // fp16 v TRANSPOSED [head][d][tok]
__device__ float g_relh[NH * NTOK * HD];               // [head][n][kh], LOG2 DOMAIN
__device__ float g_relw[NH * NTOK * HD];               // [head][n][kw], LOG2 DOMAIN
__device__ float g_po[NSPLIT * NH * NTOK * HD];        // split-KV unnormalized O
__device__ float g_pl[NSPLIT * NH * NTOK];             // split-KV partial l
// fp16 GEMM operands
__device__ __align__(16) __half g_xh[NTOK * DIM];      // x fp16
__device__ __align__(16) __half g_wqh[DIM * 3 * DIM];  // w_qkv fp16
__device__ __align__(16) __half g_wph[DIM * DIM];      // w_proj fp16
__device__ __align__(16) __half g_aoh[NTOK * DIM];     // attention out fp16
__device__ __align__(16) __half g_rph[127 * HD];       // rel_pos_h fp16
__device__ __align__(16) __half g_rpw[127 * HD];       // rel_pos_w fp16

// ---------------------------------------------------------------------------
// helpers
// ---------------------------------------------------------------------------
__device__ __forceinline__ __half2 ex2h2(__half2 x) {
    __half2 y;
    asm("ex2.approx.f16x2 %0, %1;"
        : "=r"(*reinterpret_cast<unsigned*>(&y))
        : "r"(*reinterpret_cast<unsigned*>(&x)));
    return y;
}

__device__ __forceinline__ void mma_f16(float c[4],
                                        unsigned a0, unsigned a1, unsigned a2, unsigned a3,
                                        unsigned b0, unsigned b1) {
    asm volatile(
        "mma.sync.aligned.m16n8k16.row.col.f32.f16.f16.f32 "
        "{%0,%1,%2,%3}, {%4,%5,%6,%7}, {%8,%9}, {%0,%1,%2,%3};\n"
        : "+f"(c[0]), "+f"(c[1]), "+f"(c[2]), "+f"(c[3])
        : "r"(a0), "r"(a1), "r"(a2), "r"(a3), "r"(b0), "r"(b1));
}

__device__ __forceinline__ void ldsm4(unsigned* d, uint32_t addr) {
    asm volatile("ldmatrix.sync.aligned.m8n8.x4.shared.b16 {%0,%1,%2,%3}, [%4];\n"
                 : "=r"(d[0]), "=r"(d[1]), "=r"(d[2]), "=r"(d[3]) : "r"(addr));
}

__device__ __forceinline__ void ldsm4t(unsigned* d, uint32_t addr) {
    asm volatile("ldmatrix.sync.aligned.m8n8.x4.trans.shared.b16 {%0,%1,%2,%3}, [%4];\n"
                 : "=r"(d[0]), "=r"(d[1]), "=r"(d[2]), "=r"(d[3]) : "r"(addr));
}

__device__ __forceinline__ void cp16(uint32_t dst, const void* src) {
    asm volatile("cp.async.cg.shared.global [%0], [%1], 16;\n" :: "r"(dst), "l"(src));
}
#define CP_COMMIT() asm volatile("cp.async.commit_group;\n")

// ---------------------------------------------------------------------------
// fused conversion kernel (fp32 -> fp16) for x, w_qkv, w_proj, rel_h, rel_w
// ---------------------------------------------------------------------------
#define NX4  (NTOK * DIM / 4)
#define NWQ4 (DIM * 3 * DIM / 4)
#define NWP4 (DIM * DIM / 4)
#define NRP4 (127 * HD / 4)

__global__ void conv_all_kernel(const float* __restrict__ x,
                                const float* __restrict__ wq,
                                const float* __restrict__ wp,
                                const float* __restrict__ rh,
                                const float* __restrict__ rw)
{
    int i = blockIdx.x * 256 + threadIdx.x;
    const float* src;
    __half* dst;
    int off;
    if (i < NX4)                          { src = x;  dst = g_xh;  off = i; }
    else if ((i -= NX4) < NWQ4)           { src = wq; dst = g_wqh; off = i; }
    else if ((i -= NWQ4) < NWP4)          { src = wp; dst = g_wph; off = i; }
    else if ((i -= NWP4) < NRP4)          { src = rh; dst = g_rph; off = i; }
    else if ((i -= NRP4) < NRP4)          { src = rw; dst = g_rpw; off = i; }
    else return;
    float4 v = ((const float4*)src)[off];
    __half2 h0 = __floats2half2_rn(v.x, v.y);
    __half2 h1 = __floats2half2_rn(v.z, v.w);
    ((uint2*)dst)[off] = make_uint2(*(unsigned*)&h0, *(unsigned*)&h1);
}

// ---------------------------------------------------------------------------
// fp16 x1 GEMM, 4-stage cp.async pipeline, ONE __syncthreads per TWO k16
// chunks (prefetch pair into stages freed two chunks ago).
// 128x128 tiles, 256 threads = 8 warps (4m x 2n).
// ---------------------------------------------------------------------------
#define AST_B 48
#define BST_B 272
#define A_STG_B (128 * AST_B)                  // 6144
#define B_STG_B (16 * BST_B)                   // 4352
#define GEMM_SMEM_B (4 * (A_STG_B + B_STG_B))  // 41984

__global__ void __launch_bounds__(256)
gemm_f16_kernel(const __half* __restrict__ Ah_g,
                const __half* __restrict__ Bh_g,
                const float* __restrict__ bias,
                float* __restrict__ C,
                int N, int K, int qkv_mode)
{
    extern __shared__ char gsmc[];
    char* Asm = gsmc;                      // 4 x A_STG_B
    char* Bsm = gsmc + 4 * A_STG_B;        // 4 x B_STG_B

    const int bx = blockIdx.x, by = blockIdx.y;
    const int t  = threadIdx.x;
    const int lane = t & 31, w = t >> 5;
    const int r = lane >> 2, c = lane & 3;
    const int wm = w >> 1, wn = w & 1;
    const int m0 = by * 128, n0 = bx * 128;
    const int mw = wm * 32,  nw = wn * 64;

    const int aRow  = lane & 15;
    const int aColB = (lane >> 4) * 16;
    const int bRow  = (lane & 7) + ((lane >> 3) & 1) * 8;
    const int bColB = ((lane >> 4) & 1) * 16;

    const int arow = t >> 1;
    const int acol = (t & 1) * 16;
    const int brow = t >> 4;
    const int bcol = (t & 15) * 16;

    const char* Ag = (const char*)(Ah_g + (int64_t)(m0 + arow) * K) + acol;
    const char* Bg = (const char*)(Bh_g + n0) + bcol;

    const uint32_t as_b = (uint32_t)__cvta_generic_to_shared(Asm);
    const uint32_t bs_b = (uint32_t)__cvta_generic_to_shared(Bsm);
    const uint32_t a_dst = as_b + (uint32_t)(arow * AST_B + acol);
    const uint32_t b_dst = bs_b + (uint32_t)(brow * BST_B + bcol);

    float acc[2][8][4];
#pragma unroll
    for (int mg = 0; mg < 2; mg++)
#pragma unroll
        for (int ng = 0; ng < 8; ng++)
#pragma unroll
            for (int j = 0; j < 4; j++) acc[mg][ng][j] = 0.f;

    const int nk = K / 16;   // 48 (even)

    #define G_LDG(st, i) do {                                               \
        const int kg_ = (i) * 16;                                           \
        cp16(a_dst + (uint32_t)((st) * A_STG_B), Ag + kg_ * 2);             \
        cp16(b_dst + (uint32_t)((st) * B_STG_B),                            \
             Bg + (int64_t)(kg_ + brow) * N * 2);                           \
    } while (0)

    G_LDG(0, 0); CP_COMMIT();
    G_LDG(1, 1); CP_COMMIT();

    for (int i = 0; i < nk; i++) {
        const int s = i & 3;
        if (!(i & 1)) {
            asm volatile("cp.async.wait_group 0;\n");
            __syncthreads();               // chunks i, i+1 ready; stages (i+2)&3, (i+3)&3 free
            if (i + 2 < nk) G_LDG((i + 2) & 3, i + 2);
            CP_COMMIT();
            if (i + 3 < nk) G_LDG((i + 3) & 3, i + 3);
            CP_COMMIT();
        }

        const uint32_t aB  = as_b + (uint32_t)(s * A_STG_B + (mw + aRow) * AST_B + aColB);
        const uint32_t bhB = bs_b + (uint32_t)(s * B_STG_B + bRow * BST_B + bColB);

        unsigned ah[2][4];
#pragma unroll
        for (int mg = 0; mg < 2; mg++)
            ldsm4(ah[mg], aB + (uint32_t)(mg * 16 * AST_B));
#pragma unroll
        for (int g = 0; g < 4; g++) {
            unsigned bh[4];
            ldsm4t(bh, bhB + (uint32_t)((nw + g * 16) * 2));
#pragma unroll
            for (int half = 0; half < 2; half++) {
                const unsigned b0 = bh[half * 2], b1 = bh[half * 2 + 1];
                const int ng = g * 2 + half;
#pragma unroll
                for (int mg = 0; mg < 2; mg++)
                    mma_f16(acc[mg][ng], ah[mg][0], ah[mg][1], ah[mg][2], ah[mg][3], b0, b1);
            }
        }
    }

    // ---- epilogue ----
    const float qsc = QKSCALE * LOG2E;
#pragma unroll
    for (int mg = 0; mg < 2; mg++) {
        const int row0 = m0 + mw + mg * 16 + r;
        const int row1 = row0 + 8;
#pragma unroll
        for (int ng = 0; ng < 8; ng++) {
            const int col = n0 + nw + ng * 8 + 2 * c;
            const float bs0 = bias[col], bs1 = bias[col + 1];
            float v00 = acc[mg][ng][0] + bs0, v01 = acc[mg][ng][1] + bs1;
            float v10 = acc[mg][ng][2] + bs0, v11 = acc[mg][ng][3] + bs1;
            if (qkv_mode == 0) {
                *(float2*)&C[(int64_t)row0 * N + col] = make_float2(v00, v01);
                *(float2*)&C[(int64_t)row1 * N + col] = make_float2(v10, v11);
            } else {
                const int part = col / DIM;
                const int rest = col - part * DIM;
                const int head = rest >> 6;
                const int d0   = rest & 63;
                if (part == 0) {
                    *(__half2*)&g_qh[(head * NTOK + row0) * HD + d0] =
                        __floats2half2_rn(v00 * qsc, v01 * qsc);
                    *(__half2*)&g_qh[(head * NTOK + row1) * HD + d0] =
                        __floats2half2_rn(v10 * qsc, v11 * qsc);
                } else if (part == 1) {
                    *(__half2*)&g_k[(head * NTOK + row0) * HD + d0] = __floats2half2_rn(v00, v01);
                    *(__half2*)&g_k[(head * NTOK + row1) * HD + d0] = __floats2half2_rn(v10, v11);
                } else {
                    __half* vt = g_v + head * HD * NTOK;
                    vt[(d0    ) * NTOK + row0] = __float2half_rn(v00);
                    vt[(d0 + 1) * NTOK + row0] = __float2half_rn(v01);
                    vt[(d0    ) * NTOK + row1] = __float2half_rn(v10);
                    vt[(d0 + 1) * NTOK + row1] = __float2half_rn(v11);
                }
            }
        }
    }
}

// ---------------------------------------------------------------------------
// Tensor-core rel-pos (unchanged from round 13)
// ---------------------------------------------------------------------------
__global__ void __launch_bounds__(128)
relpos_tc_kernel(const __half* __restrict__ gqh,
                 const __half* __restrict__ rph,
                 const __half* __restrict__ rpw,
                 float* __restrict__ outh,
                 float* __restrict__ outw)
{
    __shared__ __align__(16) char Asm[64 * 144];
    __shared__ __align__(16) char Bsm[64 * 144];

    const int fixed = blockIdx.x;
    const int head  = blockIdx.y;
    const int mode  = blockIdx.z;
    const int t     = threadIdx.x;
    const int lane  = t & 31;
    const int w     = t >> 5;
    const int r     = lane >> 2;
    const int c     = lane & 3;

    const __half* rp = mode ? rpw : rph;
    float* out = mode ? outw : outh;
    const __half* qbase = gqh + head * NTOK * HD;

    const uint32_t as_sm = (uint32_t)__cvta_generic_to_shared(Asm);
    const uint32_t bs_sm = (uint32_t)__cvta_generic_to_shared(Bsm);

#pragma unroll
    for (int i = 0; i < 4; i++) {
        const int ch = t + i * 128;
        const int row = ch >> 3, co = (ch & 7) * 16;
        const int tok = mode ? (row * 64 + fixed) : (fixed * 64 + row);
        cp16(as_sm + (uint32_t)(row * 144 + co), (const char*)(qbase + tok * HD) + co);
        cp16(bs_sm + (uint32_t)(row * 144 + co), (const char*)(rp + (fixed - row + 63) * HD) + co);
    }
    CP_COMMIT();
    asm volatile("cp.async.wait_group 0;\n");
    __syncthreads();

    const uint32_t aB = as_sm + (uint32_t)((w * 16 + (lane & 15)) * 144 + (lane >> 4) * 16);
    const uint32_t bB = bs_sm + (uint32_t)((lane & 15) * 144 + (lane >> 4) * 16);

    unsigned qa[4][4];
#pragma unroll
    for (int kk = 0; kk < 4; kk++)
        ldsm4(qa[kk], aB + (uint32_t)(kk * 32));

    float S[8][4];
#pragma unroll
    for (int n = 0; n < 8; n++)
#pragma unroll
        for (int j = 0; j < 4; j++) S[n][j] = 0.f;

#pragma unroll
    for (int kk = 0; kk < 4; kk++) {
#pragma unroll
        for (int g = 0; g < 4; g++) {
            unsigned bb[4];
            ldsm4(bb, bB + (uint32_t)(g * 16 * 144 + kk * 32));
            mma_f16(S[g*2],   qa[kk][0], qa[kk][1], qa[kk][2], qa[kk][3], bb[0], bb[2]);
            mma_f16(S[g*2+1], qa[kk][0], qa[kk][1], qa[kk][2], qa[kk][3], bb[1], bb[3]);
        }
    }

    const int arow0 = w * 16 + r, arow1 = arow0 + 8;
    const int tok0 = mode ? (arow0 * 64 + fixed) : (fixed * 64 + arow0);
    const int tok1 = mode ? (arow1 * 64 + fixed) : (fixed * 64 + arow1);
    float* o0 = out + (head * NTOK + tok0) * HD;
    float* o1 = out + (head * NTOK + tok1) * HD;
#pragma unroll
    for (int n = 0; n < 8; n++) {
        const int col = n * 8 + 2 * c;
        *(float2*)&o0[col] = make_float2(S[n][0] * 8.f, S[n][1] * 8.f);
        *(float2*)&o1[col] = make_float2(S[n][2] * 8.f, S[n][3] * 8.f);
    }
}

// ---------------------------------------------------------------------------
// Flash attention v15: 4-stage K/V pipeline, ONE __syncthreads per TWO
// k-tiles. Split 22/22/20 (even per CTA). Otherwise identical to v13.
// ---------------------------------------------------------------------------
#define STRH      72
#define ROW_B     144
#define KV_TILE_B (64 * ROW_B)                   // 9216 B per tile
#define PQ_B      (128 * ROW_B)                  // 18432 B
#define FLASH_SMEM_B (8 * KV_TILE_B + PQ_B)      // 92160 B
#define ONESH2 0x3C003C00u

__global__ void __launch_bounds__(128, 2)
flash_v15_kernel(const __half* __restrict__ gqh,
                 const __half* __restrict__ gk,
                 const __half* __restrict__ gvt,
                 const float* __restrict__ grh,
                 const float* __restrict__ grw,
                 float* __restrict__ po,
                 float* __restrict__ pl)
{
    extern __shared__ char smc[];
    char*   Ksc = smc;                        // 4 stages x 64 x 144B
    char*   Vsc = smc + 4 * KV_TILE_B;        // 4 stages x 64 x 144B
    __half* PQh = (__half*)(smc + 8 * KV_TILE_B);   // 128 x 72 halves (Q -> P)

    const int qt   = blockIdx.x;
    const int head = blockIdx.y;
    const int z    = blockIdx.z;      // KV third
    const int ktb  = z * 22;          // 0, 22, 44
    const int nit  = (z == 2) ? 20 : 22;   // all even
    const int t    = threadIdx.x;
    const int lane = t & 31;
    const int w    = t >> 5;
    const int r    = lane >> 2;
    const int c    = lane & 3;
    const int mbase = w * 32;

    const __half* qbh  = gqh + (head * NTOK + qt * 128) * HD;
    const __half* kb0  = gk  + head * NTOK * HD;
    const char*   vtb0 = (const char*)(gvt + head * HD * NTOK);
    const float*  rhb  = grh + (head * NTOK + qt * 128 + mbase) * HD;
    const float*  rwb  = grw + (head * NTOK + qt * 128 + mbase) * HD;

    const uint32_t ks_sm = (uint32_t)__cvta_generic_to_shared(Ksc);
    const uint32_t vs_sm = (uint32_t)__cvta_generic_to_shared(Vsc);
    const uint32_t pq_sm = (uint32_t)__cvta_generic_to_shared(PQh);

    #define LOAD_KV(st, kt) do {                                              \
        const char* kb_ = (const char*)(kb0 + (kt) * 64 * HD);                \
        const uint32_t kd_ = ks_sm + (uint32_t)((st) * KV_TILE_B);            \
        const uint32_t vd_ = vs_sm + (uint32_t)((st) * KV_TILE_B);            \
        _Pragma("unroll")                                                     \
        for (int i_ = 0; i_ < 4; i_++) {                                      \
            const int ch_ = t + i_ * 128;                                     \
            const int row_ = ch_ >> 3, co_ = (ch_ & 7) * 16;                  \
            cp16(kd_ + row_ * ROW_B + co_, kb_ + row_ * 128 + co_);           \
            cp16(vd_ + row_ * ROW_B + co_,                                    \
                 vtb0 + row_ * (NTOK * 2) + (kt) * 128 + co_);                \
        }                                                                     \
    } while (0)

    // prologue: prefetch K/V tiles ktb, ktb+1 and Q
    LOAD_KV(0, ktb);     CP_COMMIT();
    LOAD_KV(1, ktb + 1); CP_COMMIT();
#pragma unroll
    for (int i_ = 0; i_ < 8; i_++) {
        const int ch_ = t + i_ * 128;
        const int row_ = ch_ >> 3, co_ = (ch_ & 7) * 16;
        cp16(pq_sm + (uint32_t)(row_ * ROW_B + co_), (const char*)qbh + row_ * 128 + co_);
    }
    CP_COMMIT();
    asm volatile("cp.async.wait_group 0;\n");
    __syncthreads();

    // Q fragments (persist)
    const uint32_t aBase = pq_sm + (uint32_t)((mbase + (lane & 15)) * ROW_B
                                              + (lane >> 4) * 16);
    unsigned qa[2][4][4];
#pragma unroll
    for (int mb = 0; mb < 2; mb++)
#pragma unroll
        for (int kk = 0; kk < 4; kk++)
            ldsm4(qa[mb][kk], aBase + (uint32_t)(mb * 16 * ROW_B + kk * 32));
    __syncwarp();

    // rw bias (log2 domain), packed fp16x2
    __half2 rwh[2][2][8];
#pragma unroll
    for (int mb = 0; mb < 2; mb++)
#pragma unroll
        for (int rg = 0; rg < 2; rg++)
#pragma unroll
            for (int n = 0; n < 8; n++) {
                float2 v = *(const float2*)&rwb[(mb * 16 + rg * 8 + r) * HD + n * 8 + 2 * c];
                rwh[mb][rg][n] = __floats2half2_rn(v.x, v.y);
            }

    float O[2][8][4];
#pragma unroll
    for (int mb = 0; mb < 2; mb++)
#pragma unroll
        for (int n = 0; n < 8; n++)
#pragma unroll
            for (int j = 0; j < 4; j++) O[mb][n][j] = 0.f;
    float lacc[2][4];
#pragma unroll
    for (int mb = 0; mb < 2; mb++)
#pragma unroll
        for (int j = 0; j < 4; j++) lacc[mb][j] = 0.f;

    for (int it = 0; it < nit; it++) {
        const int kt = ktb + it;
        const int s  = it & 3;

        if (!(it & 1)) {
            asm volatile("cp.async.wait_group 0;\n");
            __syncthreads();   // tiles it, it+1 ready; stages (it+2)&3, (it+3)&3 free
            if (it + 2 < nit) LOAD_KV((it + 2) & 3, kt + 2);
            CP_COMMIT();
            if (it + 3 < nit) LOAD_KV((it + 3) & 3, kt + 3);
            CP_COMMIT();
        }

        float rh[2][2];
#pragma unroll
        for (int mb = 0; mb < 2; mb++) {
            rh[mb][0] = __ldg(&rhb[(mb * 16 + r) * HD + kt])     - M0SHIFT;
            rh[mb][1] = __ldg(&rhb[(mb * 16 + 8 + r) * HD + kt]) - M0SHIFT;
        }

        const uint32_t kS = ks_sm + (uint32_t)(s * KV_TILE_B)
                              + (lane & 15) * ROW_B + (lane >> 4) * 16;
        const uint32_t vS = vs_sm + (uint32_t)(s * KV_TILE_B)
                              + (lane & 15) * ROW_B + (lane >> 4) * 16;

        // ---- S = Q K^T over full 64 keys ----
        float S[2][8][4];
#pragma unroll
        for (int mb = 0; mb < 2; mb++)
#pragma unroll
            for (int n = 0; n < 8; n++)
#pragma unroll
                for (int j = 0; j < 4; j++) S[mb][n][j] = 0.f;

#pragma unroll
        for (int kk = 0; kk < 4; kk++) {
#pragma unroll
            for (int g = 0; g < 4; g++) {
                unsigned bb[4];
                ldsm4(bb, kS + (uint32_t)(g * 16 * ROW_B + kk * 32));
                mma_f16(S[0][g*2],   qa[0][kk][0], qa[0][kk][1], qa[0][kk][2], qa[0][kk][3], bb[0], bb[2]);
                mma_f16(S[0][g*2+1], qa[0][kk][0], qa[0][kk][1], qa[0][kk][2], qa[0][kk][3], bb[1], bb[3]);
                mma_f16(S[1][g*2],   qa[1][kk][0], qa[1][kk][1], qa[1][kk][2], qa[1][kk][3], bb[0], bb[2]);
                mma_f16(S[1][g*2+1], qa[1][kk][0], qa[1][kk][1], qa[1][kk][2], qa[1][kk][3], bb[1], bb[3]);
            }
        }

        // ---- fixed-shift softmax: p = 2^(S + rh' + rw'), f16x2 exp ----
#pragma unroll
        for (int mb = 0; mb < 2; mb++) {
            const float a0 = rh[mb][0];
            const float a1 = rh[mb][1];
            __half* prow0 = PQh + (mbase + mb * 16 + r) * STRH + 2 * c;
            __half* prow1 = prow0 + 8 * STRH;
#pragma unroll
            for (int n = 0; n < 8; n++) {
                __half2 h01 = __floats2half2_rn(S[mb][n][0] + a0, S[mb][n][1] + a0);
                __half2 h23 = __floats2half2_rn(S[mb][n][2] + a1, S[mb][n][3] + a1);
                __half2 p01 = ex2h2(__hadd2(h01, rwh[mb][0][n]));
                __half2 p23 = ex2h2(__hadd2(h23, rwh[mb][1][n]));
                *(__half2*)(prow0 + n * 8) = p01;
                *(__half2*)(prow1 + n * 8) = p23;
            }
        }
        __syncwarp();   // P rows warp-private

        // ---- O += P V; l += P * ones ----
#pragma unroll
        for (int kk2 = 0; kk2 < 4; kk2++) {
            unsigned pa[2][4];
            ldsm4(pa[0], aBase + (uint32_t)(kk2 * 32));
            ldsm4(pa[1], aBase + (uint32_t)(16 * ROW_B + kk2 * 32));
            mma_f16(lacc[0], pa[0][0], pa[0][1], pa[0][2], pa[0][3], ONESH2, ONESH2);
            mma_f16(lacc[1], pa[1][0], pa[1][1], pa[1][2], pa[1][3], ONESH2, ONESH2);
#pragma unroll
            for (int p = 0; p < 4; p++) {
                unsigned vv[4];
                ldsm4(vv, vS + (uint32_t)(p * 16 * ROW_B + kk2 * 32));
                mma_f16(O[0][p*2],   pa[0][0], pa[0][1], pa[0][2], pa[0][3], vv[0], vv[2]);
                mma_f16(O[0][p*2+1], pa[0][0], pa[0][1], pa[0][2], pa[0][3], vv[1], vv[3]);
                mma_f16(O[1][p*2],   pa[1][0], pa[1][1], pa[1][2], pa[1][3], vv[0], vv[2]);
                mma_f16(O[1][p*2+1], pa[1][0], pa[1][1], pa[1][2], pa[1][3], vv[1], vv[3]);
            }
        }
        __syncwarp();   // P reads done before next tile's stores
    }

    // ---- epilogue ----
    const int pz = z * NH * NTOK + head * NTOK;
#pragma unroll
    for (int mb = 0; mb < 2; mb++) {
        const int row0 = qt * 128 + mbase + mb * 16 + r;
        const int row1 = row0 + 8;
        if (c == 0) {
            pl[pz + row0] = lacc[mb][0];
            pl[pz + row1] = lacc[mb][2];
        }
#pragma unroll
        for (int n = 0; n < 8; n++) {
            const int col = n * 8 + 2 * c;
            *(float2*)&po[(pz + row0) * HD + col] = make_float2(O[mb][n][0], O[mb][n][1]);
            *(float2*)&po[(pz + row1) * HD + col] = make_float2(O[mb][n][2], O[mb][n][3]);
        }
    }
}

// ---------------------------------------------------------------------------
// merge the three KV-third partials -> g_aoh (fp16, feeds proj GEMM)
// ---------------------------------------------------------------------------
__global__ void merge_kernel(const float* __restrict__ po,
                             const float* __restrict__ pl,
                             __half* __restrict__ aoh)
{
    const int gid = blockIdx.x * 256 + threadIdx.x;
    const int dp  = (gid & 7) * 8;
    const int hr  = gid >> 3;
    const int head = hr >> 12, row = hr & 4095;
    const int S = NH * NTOK;

    const float inv = 1.0f / (pl[hr] + pl[S + hr] + pl[2 * S + hr]);

    const float* o0 = po + (size_t)hr * HD + dp;
    const float* o1 = po + (size_t)(S + hr) * HD + dp;
    const float* o2 = po + (size_t)(2 * S + hr) * HD + dp;
    __half* dst = aoh + row * DIM + head * HD + dp;

    uint4 outw;
    unsigned* ow = (unsigned*)&outw;
#pragma unroll
    for (int j = 0; j < 8; j += 2) {
        float x = (o0[j]     + o1[j]     + o2[j])     * inv;
        float y = (o0[j + 1] + o1[j + 1] + o2[j + 1]) * inv;
        __half2 h = __floats2half2_rn(x, y);
        ow[j >> 1] = *(unsigned*)&h;
    }
    *(uint4*)dst = outw;
}

// ---------------------------------------------------------------------------
extern "C" void kernel_launch(void* const* d_in, const int* in_sizes, int n_in,
                              void* d_out, int out_size)
{
    const float* x        = (const float*)d_in[0];
    const float* w_qkv    = (const float*)d_in[1];
    const float* b_qkv    = (const float*)d_in[2];
    const float* w_proj   = (const float*)d_in[3];
    const float* b_proj   = (const float*)d_in[4];
    const float* rel_h    = (const float*)d_in[5];
    const float* rel_w    = (const float*)d_in[6];
    float* out = (float*)d_out;

    float *grh, *grw, *gpo, *gpl;
    __half *gqh, *gk, *gv, *gxh, *gwqh, *gwph, *gaoh, *grph, *grpw;
    cudaGetSymbolAddress((void**)&gqh,  g_qh);
    cudaGetSymbolAddress((void**)&gk,   g_k);
    cudaGetSymbolAddress((void**)&gv,   g_v);
    cudaGetSymbolAddress((void**)&grh,  g_relh);
    cudaGetSymbolAddress((void**)&grw,  g_relw);
    cudaGetSymbolAddress((void**)&gpo,  g_po);
    cudaGetSymbolAddress((void**)&gpl,  g_pl);
    cudaGetSymbolAddress((void**)&gxh,  g_xh);
    cudaGetSymbolAddress((void**)&gwqh, g_wqh);
    cudaGetSymbolAddress((void**)&gwph, g_wph);
    cudaGetSymbolAddress((void**)&gaoh, g_aoh);
    cudaGetSymbolAddress((void**)&grph, g_rph);
    cudaGetSymbolAddress((void**)&grpw, g_rpw);

    // 0) fused conversion of all operands to fp16
    const int NCONV = NX4 + NWQ4 + NWP4 + 2 * NRP4;
    conv_all_kernel<<<(NCONV + 255) / 256, 256>>>(x, w_qkv, w_proj, rel_h, rel_w);

    cudaFuncSetAttribute(gemm_f16_kernel,
                         cudaFuncAttributeMaxDynamicSharedMemorySize, GEMM_SMEM_B);

    // 1) QKV GEMM (fp16 x1, 4-stage cp.async, barrier per 2 chunks)
    gemm_f16_kernel<<<dim3(3 * DIM / 128, NTOK / 128), 256, GEMM_SMEM_B>>>(
        gxh, gwqh, b_qkv, nullptr, 3 * DIM, DIM, 1);

    // 2) rel_h / rel_w via tensor cores
    relpos_tc_kernel<<<dim3(GRID_HW, NH, 2), 128>>>(gqh, grph, grpw, grh, grw);

    // 3) flash attention v15 (4-stage, barrier per 2 tiles, split 22/22/20)
    cudaFuncSetAttribute(flash_v15_kernel,
                         cudaFuncAttributeMaxDynamicSharedMemorySize, FLASH_SMEM_B);
    flash_v15_kernel<<<dim3(NTOK / 128, NH, NSPLIT), 128, FLASH_SMEM_B>>>(
        gqh, gk, gv, grh, grw, gpo, gpl);

    // 4) merge partials -> fp16 ao
    merge_kernel<<<NH * NTOK * 8 / 256, 256>>>(gpo, gpl, gaoh);

    // 5) output projection (fp16 x1, 4-stage cp.async)
    gemm_f16_kernel<<<dim3(DIM / 128, NTOK / 128), 256, GEMM_SMEM_B>>>(
        gaoh, gwph, b_proj, out, DIM, DIM, 0);
}